// round 6
// baseline (speedup 1.0000x reference)
#include <cuda_runtime.h>
#include <cuda_bf16.h>
#include <cstdint>

typedef unsigned long long ull;
typedef long long ll;
typedef unsigned short u16;
typedef unsigned int u32;

#define UDIM 1024
#define BATCH 32
#define TDIM 2048
#define CH 8
#define NCH (TDIM / CH)          // 256
#define KTOT 3072

// ---------------- scratch (device globals; no runtime alloc) ----------------
__device__ u16   g_Xhi[(size_t)BATCH * TDIM * UDIM];
__device__ u16   g_Xlo[(size_t)BATCH * TDIM * UDIM];
__device__ u16   g_UAhi[NCH * BATCH * UDIM], g_UAlo[NCH * BATCH * UDIM];
__device__ u16   g_UBhi[NCH * BATCH * UDIM], g_UBlo[NCH * BATCH * UDIM];
__device__ u16   g_KThi[UDIM * UDIM], g_KTlo[UDIM * UDIM];
__device__ u16   g_SPhi[CH * UDIM * UDIM], g_SPlo[CH * UDIM * UDIM];  // S^1..S^8
__device__ u16   g_RPhi[3 * UDIM * UDIM], g_RPlo[3 * UDIM * UDIM];    // R^1,R^2,R^4
__device__ float g_PowF[4 * UDIM * UDIM];   // fp32 S^5..S^8 (S^8 = rows 3072..4095)
__device__ float g_gbuf[NCH * BATCH * UDIM];

#define MAX_BAR 2048
__device__ volatile unsigned g_bar[MAX_BAR];

__global__ void __launch_bounds__(256) bar_reset_kernel() {
    int i = blockIdx.x * blockDim.x + threadIdx.x;
    if (i < MAX_BAR) *(unsigned*)&g_bar[i] = 0u;
}
__global__ void __launch_bounds__(256) copy_h0_kernel(const float* __restrict__ h0,
                                                      float* __restrict__ g) {
    int i = blockIdx.x * blockDim.x + threadIdx.x;
    if (i < BATCH * UDIM) g[i] = h0[i];
}

// ---------------- helpers ----------------
__device__ __forceinline__ u32 smem_u32(const void* p) {
    u32 a;
    asm("{ .reg .u64 t; cvta.to.shared.u64 t, %1; cvt.u32.u64 %0, t; }"
        : "=r"(a) : "l"(p));
    return a;
}
#define SWZ(o) ((o) ^ (((o) >> 3) & 0x70))

__device__ __forceinline__ void bsplit(float v, u16& h, u16& l) {
    __nv_bfloat16 bh = __float2bfloat16_rn(v);
    float r = v - __bfloat162float(bh);
    __nv_bfloat16 bl = __float2bfloat16_rn(r);
    h = __bfloat16_as_ushort(bh);
    l = __bfloat16_as_ushort(bl);
}

__device__ __forceinline__ void ldsm4(u32 addr, u32& r0, u32& r1, u32& r2, u32& r3) {
    asm volatile("ldmatrix.sync.aligned.m8n8.x4.shared.b16 {%0,%1,%2,%3}, [%4];"
                 : "=r"(r0), "=r"(r1), "=r"(r2), "=r"(r3) : "r"(addr));
}
__device__ __forceinline__ void mma16816(float* d, const u32* a, const u32* b) {
    asm volatile(
        "mma.sync.aligned.m16n8k16.row.col.f32.bf16.bf16.f32 "
        "{%0,%1,%2,%3}, {%4,%5,%6,%7}, {%8,%9}, {%0,%1,%2,%3};"
        : "+f"(d[0]), "+f"(d[1]), "+f"(d[2]), "+f"(d[3])
        : "r"(a[0]), "r"(a[1]), "r"(a[2]), "r"(a[3]), "r"(b[0]), "r"(b[1]));
}

// ------------- split_gather: fp32 strided rows -> bf16 hi/lo natural -------
__global__ void __launch_bounds__(256) split_gather_kernel(
    const float* __restrict__ src, ll sB, ll sC,
    u16* __restrict__ hi, u16* __restrict__ lo)
{
    int m = blockIdx.x;
    int k = threadIdx.x * 4;
    ll off = (ll)(m & 31) * sB + (ll)(m >> 5) * sC + k;
    float4 v = *(const float4*)(src + off);
    u16 h0, h1, h2, h3, l0, l1, l2, l3;
    bsplit(v.x, h0, l0); bsplit(v.y, h1, l1);
    bsplit(v.z, h2, l2); bsplit(v.w, h3, l3);
    ll doff = (ll)m * 1024 + k;
    *(ushort4*)(hi + doff) = make_ushort4(h0, h1, h2, h3);
    *(ushort4*)(lo + doff) = make_ushort4(l0, l1, l2, l3);
}

// ------------- transpose_split: fp32 W[k][n] -> bf16 hi/lo of W^T [n][k] ----
__global__ void __launch_bounds__(256) transpose_split_kernel(
    const float* __restrict__ src, u16* __restrict__ thi, u16* __restrict__ tlo)
{
    __shared__ float tile[32][33];
    int bx = blockIdx.x * 32;   // n
    int by = blockIdx.y * 32;   // k
    int tx = threadIdx.x & 31;
    int ty = threadIdx.x >> 5;
#pragma unroll
    for (int i = 0; i < 32; i += 8)
        tile[ty + i][tx] = src[(ll)(by + ty + i) * 1024 + bx + tx];
    __syncthreads();
#pragma unroll
    for (int i = 0; i < 32; i += 8) {
        u16 h, l;
        bsplit(tile[tx][ty + i], h, l);
        ll off = (ll)(bx + ty + i) * 1024 + (by + tx);
        thi[off] = h;
        tlo[off] = l;
    }
}

// ---------------------------------------------------------------------------
// tgemm: C[m][n] = sum_{k<1024} Af[m][k]*Bf[n][k] via bf16 split, K'=3072:
//   region0 Ahi*Bhi, region1 Alo*Bhi, region2 Ahi*Blo (per 64-wide K chunk).
// mma.sync m16n8k16 bf16, CTA 128x128, BK=64 (SW128 rows), 3-stage cp.async.
// Epilogue: +Add (strided/shift), fp32 out (strided b/c via &31,>>5), bf16
// hi/lo re-split (natural). All outputs nullable.
// ---------------------------------------------------------------------------
#define TG_STAGE 32768
#define TG_SMEM (3 * TG_STAGE)
#define TG_NCHK (KTOT / 64)

__global__ void __launch_bounds__(256) tgemm_kernel(
    const u16* __restrict__ Ahi, const u16* __restrict__ Alo,
    const u16* __restrict__ Bhi, const u16* __restrict__ Blo,
    const float* __restrict__ Add, int adShift, ll adSB, ll adSC,
    float* __restrict__ OutF, ll ofSB, ll ofSC,
    u16* __restrict__ OBhi, u16* __restrict__ OBlo)
{
    extern __shared__ char smraw[];
    const u32 smbase = smem_u32(smraw);

    const int tid  = threadIdx.x;
    const int wid  = tid >> 5;
    const int lane = tid & 31;
    const ll mBase = (ll)blockIdx.y * 128;
    const ll nBase = (ll)blockIdx.x * 128;

    const int wm = (wid >> 1) * 32;
    const int wn = (wid & 1) * 64;

    float acc[2][8][4];
#pragma unroll
    for (int i = 0; i < 2; i++)
#pragma unroll
        for (int j = 0; j < 8; j++)
#pragma unroll
            for (int q = 0; q < 4; q++) acc[i][j][q] = 0.0f;

    auto load_chunk = [&](int c, int s) {
        const int reg = c >> 4;
        const u16* aptr = (reg == 1) ? Alo : Ahi;
        const u16* bptr = (reg == 2) ? Blo : Bhi;
        const ll kbase = (ll)(c & 15) * 64;
        u32 sa = smbase + (u32)s * TG_STAGE;
        u32 sb = sa + 16384;
#pragma unroll
        for (int i = 0; i < 4; i++) {
            int idx = i * 256 + tid;
            int row = idx >> 3;
            int cc  = (idx & 7) * 16;
            ll  kel = kbase + (idx & 7) * 8;
            asm volatile("cp.async.cg.shared.global [%0], [%1], 16;"
                :: "r"(sa + SWZ((u32)(row * 128 + cc))),
                   "l"((ull)(uintptr_t)(aptr + (mBase + row) * 1024 + kel)));
            asm volatile("cp.async.cg.shared.global [%0], [%1], 16;"
                :: "r"(sb + SWZ((u32)(row * 128 + cc))),
                   "l"((ull)(uintptr_t)(bptr + (nBase + row) * 1024 + kel)));
        }
        asm volatile("cp.async.commit_group;" ::: "memory");
    };

    load_chunk(0, 0);
    load_chunk(1, 1);

    const int aRow = (lane & 15);
    const int aKb  = (lane >> 4) * 16;
    const int bRow = (lane & 7) + ((lane >> 4) << 3);
    const int bKb  = ((lane >> 3) & 1) * 16;

#pragma unroll 1
    for (int c = 0; c < TG_NCHK; c++) {
        if (c + 2 < TG_NCHK) {
            asm volatile("cp.async.wait_group 1;" ::: "memory");
        } else {
            asm volatile("cp.async.wait_group 0;" ::: "memory");
        }
        __syncthreads();
        if (c + 2 < TG_NCHK) load_chunk(c + 2, (c + 2) % 3);

        u32 sa = smbase + (u32)(c % 3) * TG_STAGE;
        u32 sb = sa + 16384;

#pragma unroll
        for (int k16 = 0; k16 < 4; k16++) {
            const int kb = k16 * 32;
            u32 areg[2][4];
#pragma unroll
            for (int i = 0; i < 2; i++) {
                u32 ad = sa + SWZ((u32)((wm + i * 16 + aRow) * 128 + kb + aKb));
                ldsm4(ad, areg[i][0], areg[i][1], areg[i][2], areg[i][3]);
            }
            u32 breg[4][4];
#pragma unroll
            for (int j16 = 0; j16 < 4; j16++) {
                u32 bd = sb + SWZ((u32)((wn + j16 * 16 + bRow) * 128 + kb + bKb));
                ldsm4(bd, breg[j16][0], breg[j16][1], breg[j16][2], breg[j16][3]);
            }
#pragma unroll
            for (int i = 0; i < 2; i++)
#pragma unroll
                for (int j = 0; j < 8; j++)
                    mma16816(acc[i][j], areg[i], &breg[j >> 1][(j & 1) * 2]);
        }
        __syncthreads();
    }

    const int g  = lane >> 2;
    const int tg = (lane & 3) * 2;

#pragma unroll
    for (int i = 0; i < 2; i++) {
#pragma unroll
        for (int half = 0; half < 2; half++) {
            ll m = mBase + wm + i * 16 + g + half * 8;
            const float* addp = Add ?
                Add + (m & ((1 << adShift) - 1)) * adSB + (m >> adShift) * adSC + nBase
                : (const float*)0;
            float* ofp = OutF ?
                OutF + (m & 31) * ofSB + (m >> 5) * ofSC + nBase : (float*)0;
            u16* obh = OBhi ? OBhi + m * 1024 + nBase : (u16*)0;
            u16* obl = OBlo ? OBlo + m * 1024 + nBase : (u16*)0;
#pragma unroll
            for (int j = 0; j < 8; j++) {
                int n = wn + j * 8 + tg;
                float v0 = acc[i][j][half * 2 + 0];
                float v1 = acc[i][j][half * 2 + 1];
                if (addp) {
                    float2 a = *(const float2*)(addp + n);
                    v0 += a.x; v1 += a.y;
                }
                if (ofp)
                    *(float2*)(ofp + n) = make_float2(v0, v1);
                if (obh) {
                    u16 h0, h1, l0, l1;
                    bsplit(v0, h0, l0);
                    bsplit(v1, h1, l1);
                    *(ushort2*)(obh + n) = make_ushort2(h0, h1);
                    *(ushort2*)(obl + n) = make_ushort2(l0, l1);
                }
            }
        }
    }
}

// ---------------------------------------------------------------------------
// phase2: serial carry chain g[c+1] = g[c] @ R^CH + u[c]  (fp32, persistent)
// RC passed as S^CH = (R^CH)^T fp32 natural [n][k] (contiguous row loads).
// u read strided from `out` rows (phase-1 u_{CH-1} already in place there).
// ---------------------------------------------------------------------------
__device__ __forceinline__ void ffma2(ull& d, ull a, ull b) {
    asm volatile("fma.rn.f32x2 %0, %1, %2, %0;" : "+l"(d) : "l"(a), "l"(b));
}
__device__ __forceinline__ float2 u2f2(ull v) {
    float2 f;
    f.x = __uint_as_float((unsigned)(v & 0xffffffffull));
    f.y = __uint_as_float((unsigned)(v >> 32));
    return f;
}
__device__ __forceinline__ float4 ldcg4(const float* p) {
    float4 v;
    asm volatile("ld.global.cg.v4.f32 {%0,%1,%2,%3}, [%4];"
                 : "=f"(v.x), "=f"(v.y), "=f"(v.z), "=f"(v.w) : "l"(p));
    return v;
}
#define P2_RPAD 1028
#define P2_HPAD 1032
#define P2_HS_OFF (32 * P2_RPAD)
#define P2_SMEM_FLOATS (32 * P2_RPAD + 8 * P2_HPAD)
#define P2_CTAS 128

__global__ void __launch_bounds__(256) phase2_kernel(
    const float* __restrict__ ST,   // S^CH fp32, [n][k]
    const float* __restrict__ u, ll uSB, ll uSC,
    float* __restrict__ g, int steps)
{
    extern __shared__ float sm[];
    const int tid = threadIdx.x;
    const int col0 = (blockIdx.x & 31) * 32;
    const int b0   = (blockIdx.x >> 5) * 8;

    // Load S^CH rows col0..col0+31 (contiguous, coalesced)
    for (int idx = tid; idx < 32 * 1024; idx += 256) {
        int j = idx >> 10, k = idx & 1023;
        sm[j * P2_RPAD + k] = ST[(size_t)(col0 + j) * 1024 + k];
    }
    __syncthreads();

    const int j = tid & 31;
    const int b = tid >> 5;
    const float* Rrow = &sm[j * P2_RPAD];
    const float* hrow = &sm[P2_HS_OFF + b * P2_HPAD];
    const unsigned P = gridDim.x;

    for (int c = 0; c < steps; c++) {
        const float* gsrc = g + (size_t)c * (BATCH * UDIM);
        for (int i = tid; i < 2048; i += 256) {
            int bb = i >> 8, kk = (i & 255) * 4;
            float4 v = ldcg4(gsrc + (size_t)(b0 + bb) * UDIM + kk);
            *(float4*)&sm[P2_HS_OFF + bb * P2_HPAD + kk] = v;
        }
        __syncthreads();

        ull a0 = 0, a1 = 0, a2 = 0, a3 = 0;
#pragma unroll 4
        for (int k = 0; k < 1024; k += 8) {
            ulonglong2 h01 = *(const ulonglong2*)(hrow + k);
            ulonglong2 h23 = *(const ulonglong2*)(hrow + k + 4);
            ulonglong2 r01 = *(const ulonglong2*)(Rrow + k);
            ulonglong2 r23 = *(const ulonglong2*)(Rrow + k + 4);
            ffma2(a0, h01.x, r01.x); ffma2(a1, h01.y, r01.y);
            ffma2(a2, h23.x, r23.x); ffma2(a3, h23.y, r23.y);
        }
        float2 f0 = u2f2(a0), f1 = u2f2(a1), f2 = u2f2(a2), f3 = u2f2(a3);
        float sum = ((f0.x + f0.y) + (f1.x + f1.y)) +
                    ((f2.x + f2.y) + (f3.x + f3.y));

        float uv = __ldg(u + (ll)(b0 + b) * uSB + (ll)c * uSC + col0 + j);
        g[(size_t)(c + 1) * (BATCH * UDIM) + (size_t)(b0 + b) * UDIM + col0 + j] =
            sum + uv;

        __threadfence();
        __syncthreads();
        if (tid == 0) {
            unsigned arrived = atomicAdd((unsigned*)&g_bar[c], 1u) + 1u;
            if (arrived < P)
                while (g_bar[c] < P) __nanosleep(64);
            __threadfence();
        }
        __syncthreads();
    }
}

// ---------------------------------------------------------------------------
extern "C" void kernel_launch(void* const* d_in, const int* in_sizes, int n_in,
                              void* d_out, int out_size)
{
    const float* x    = (const float*)d_in[0];
    const float* h0   = (const float*)d_in[1];
    const float* cst  = (const float*)d_in[2];
    const float* kern = (const float*)d_in[3];
    const float* rker = (const float*)d_in[4];
    float* out = (float*)d_out;

    const ll TU = (ll)TDIM * UDIM;   // out stride per batch
    const ll CU = (ll)CH * UDIM;     // out stride per chunk (8 rows)
    const ll SL = (ll)UDIM * UDIM;   // power-slot stride

    u16 *Xhi, *Xlo, *UAhi, *UAlo, *UBhi, *UBlo, *KThi, *KTlo;
    u16 *SPhi, *SPlo, *RPhi, *RPlo;
    float *PowF, *gbuf;
    cudaGetSymbolAddress((void**)&Xhi, g_Xhi);   cudaGetSymbolAddress((void**)&Xlo, g_Xlo);
    cudaGetSymbolAddress((void**)&UAhi, g_UAhi); cudaGetSymbolAddress((void**)&UAlo, g_UAlo);
    cudaGetSymbolAddress((void**)&UBhi, g_UBhi); cudaGetSymbolAddress((void**)&UBlo, g_UBlo);
    cudaGetSymbolAddress((void**)&KThi, g_KThi); cudaGetSymbolAddress((void**)&KTlo, g_KTlo);
    cudaGetSymbolAddress((void**)&SPhi, g_SPhi); cudaGetSymbolAddress((void**)&SPlo, g_SPlo);
    cudaGetSymbolAddress((void**)&RPhi, g_RPhi); cudaGetSymbolAddress((void**)&RPlo, g_RPlo);
    cudaGetSymbolAddress((void**)&PowF, g_PowF);
    cudaGetSymbolAddress((void**)&gbuf, g_gbuf);

    cudaFuncSetAttribute(tgemm_kernel,
        cudaFuncAttributeMaxDynamicSharedMemorySize, TG_SMEM);
    cudaFuncSetAttribute(phase2_kernel,
        cudaFuncAttributeMaxDynamicSharedMemorySize, P2_SMEM_FLOATS * 4);

    bar_reset_kernel<<<(MAX_BAR + 255) / 256, 256>>>();

    // input splits: X natural; S^1 = R^T (slot 0 of SP); R^1 (slot 0 of RP);
    // K^T for phase 0
    split_gather_kernel<<<BATCH * TDIM, 256>>>(x, 1024, 32768, Xhi, Xlo);
    dim3 gt(32, 32);
    transpose_split_kernel<<<gt, 256>>>(kern, KThi, KTlo);
    transpose_split_kernel<<<gt, 256>>>(rker, SPhi, SPlo);            // S^1
    split_gather_kernel<<<UDIM, 256>>>(rker, 1024, 32768, RPhi, RPlo); // R^1
    copy_h0_kernel<<<(BATCH * UDIM + 255) / 256, 256>>>(h0, gbuf);

    // phase 0: xw = x @ kernel + const -> out (rows m = b*T + t)
    {
        dim3 g0(8, 512);
        tgemm_kernel<<<g0, 256, TG_SMEM>>>(Xhi, Xlo, KThi, KTlo,
            cst, 11, 0, 1024,
            out, 1024, 32768,
            nullptr, nullptr);
    }

    // power chain (log depth):
    //   S^{a+b} = S^a * (B = R^b),  R^{a+b} = R^a * (B = S^b)
    {
        dim3 g1(8, 8), g2(8, 16), g4(8, 32);
        // S^2 = S^1 * R^1 -> SP slot 1
        tgemm_kernel<<<g1, 256, TG_SMEM>>>(SPhi, SPlo, RPhi, RPlo,
            nullptr, 5, 0, 0, nullptr, 0, 0, SPhi + SL, SPlo + SL);
        // R^2 = R^1 * S^1 -> RP slot 1
        tgemm_kernel<<<g1, 256, TG_SMEM>>>(RPhi, RPlo, SPhi, SPlo,
            nullptr, 5, 0, 0, nullptr, 0, 0, RPhi + SL, RPlo + SL);
        // S^3,S^4 = [S^1,S^2] * R^2 -> SP slots 2,3
        tgemm_kernel<<<g2, 256, TG_SMEM>>>(SPhi, SPlo, RPhi + SL, RPlo + SL,
            nullptr, 5, 0, 0, nullptr, 0, 0, SPhi + 2 * SL, SPlo + 2 * SL);
        // R^4 = R^2 * S^2 -> RP slot 2
        tgemm_kernel<<<g1, 256, TG_SMEM>>>(RPhi + SL, RPlo + SL, SPhi + SL, SPlo + SL,
            nullptr, 5, 0, 0, nullptr, 0, 0, RPhi + 2 * SL, RPlo + 2 * SL);
        // S^5..S^8 = [S^1..S^4] * R^4 -> SP slots 4..7, fp32 copy -> PowF
        tgemm_kernel<<<g4, 256, TG_SMEM>>>(SPhi, SPlo, RPhi + 2 * SL, RPlo + 2 * SL,
            nullptr, 5, 0, 0, PowF, 1024, 32768, SPhi + 4 * SL, SPlo + 4 * SL);
    }

    // gather xw rows at t = c*CH (chunk heads), split -> UA  (m = c*32+b)
    split_gather_kernel<<<NCH * BATCH, 256>>>(out, TU, CU, UAhi, UAlo);

    // phase 1: Horner u_j = u_{j-1} @ R + xw_{c*CH+j}, j = 1..CH-1.
    // Each step writes u_j fp32 into out rows t = c*CH+j (prefix values),
    // and bf16 split for the next step (except the last).
    {
        dim3 gp(8, 64);   // M = 8192
        for (int jj = 1; jj < CH; jj++) {
            const u16* ah = (jj & 1) ? UAhi : UBhi;
            const u16* al = (jj & 1) ? UAlo : UBlo;
            u16* oh = (jj & 1) ? UBhi : UAhi;
            u16* ol = (jj & 1) ? UBlo : UAlo;
            bool last = (jj == CH - 1);
            tgemm_kernel<<<gp, 256, TG_SMEM>>>(ah, al, SPhi, SPlo,
                out + (size_t)jj * UDIM, 5, TU, CU,
                out + (size_t)jj * UDIM, TU, CU,
                last ? nullptr : oh, last ? nullptr : ol);
        }
    }

    // phase 2: g[c+1] = g[c] @ R^CH + u_{CH-1,c}  (NCH-1 serial steps)
    // S^CH fp32 = PowF rows 3072..4095; u read from out rows t = c*CH + CH-1.
    phase2_kernel<<<P2_CTAS, 256, P2_SMEM_FLOATS * 4>>>(
        PowF + (size_t)3072 * 1024,
        out + (size_t)(CH - 1) * UDIM, TU, CU,
        gbuf, NCH - 1);

    // split carries -> UA  (m = c*32+b)
    split_gather_kernel<<<NCH * BATCH, 256>>>(gbuf, 1024, 32768, UAhi, UAlo);

    // phase 3 (single GEMM): out_{c*CH+j} += g_c @ R^{j+1} for all j at once.
    // A = g split (M = 8192), B = stacked S^1..S^CH (N = 8192). The N axis
    // maps contiguously into out (chunk rows are time-contiguous):
    // offset = b*TU + c*CU + nGlobal.
    {
        dim3 gp(CH * 1024 / 128, 64);   // (64, 64) = 4096 CTAs
        tgemm_kernel<<<gp, 256, TG_SMEM>>>(UAhi, UAlo, SPhi, SPlo,
            out, 5, TU, CU,
            out, TU, CU,
            nullptr, nullptr);
    }
}

// round 7
// speedup vs baseline: 1.1858x; 1.1858x over previous
#include <cuda_runtime.h>
#include <cuda_bf16.h>
#include <cstdint>

typedef unsigned long long ull;
typedef long long ll;
typedef unsigned short u16;
typedef unsigned int u32;

#define UDIM 1024
#define BATCH 32
#define TDIM 2048
#define CH 16
#define NCH (TDIM / CH)          // 128
#define KTOT 3072

// ---------------- scratch (device globals; no runtime alloc) ----------------
__device__ u16   g_Xhi[(size_t)BATCH * TDIM * UDIM];
__device__ u16   g_Xlo[(size_t)BATCH * TDIM * UDIM];
__device__ u16   g_UAhi[NCH * BATCH * UDIM], g_UAlo[NCH * BATCH * UDIM];
__device__ u16   g_UBhi[NCH * BATCH * UDIM], g_UBlo[NCH * BATCH * UDIM];
__device__ u16   g_KThi[UDIM * UDIM], g_KTlo[UDIM * UDIM];
__device__ u16   g_SPhi[CH * UDIM * UDIM], g_SPlo[CH * UDIM * UDIM];  // S^1..S^16
__device__ u16   g_RPhi[4 * UDIM * UDIM], g_RPlo[4 * UDIM * UDIM];    // R^1,2,4,8
__device__ float g_PowF[8 * UDIM * UDIM];   // fp32 S^9..S^16 (S^16 = rows 7168+)
__device__ float g_gbuf[NCH * BATCH * UDIM];

#define MAX_BAR 2048
__device__ volatile unsigned g_bar[MAX_BAR];

__global__ void __launch_bounds__(256) bar_reset_kernel() {
    int i = blockIdx.x * blockDim.x + threadIdx.x;
    if (i < MAX_BAR) *(unsigned*)&g_bar[i] = 0u;
}
__global__ void __launch_bounds__(256) copy_h0_kernel(const float* __restrict__ h0,
                                                      float* __restrict__ g) {
    int i = blockIdx.x * blockDim.x + threadIdx.x;
    if (i < BATCH * UDIM) g[i] = h0[i];
}

// ---------------- helpers ----------------
__device__ __forceinline__ u32 smem_u32(const void* p) {
    u32 a;
    asm("{ .reg .u64 t; cvta.to.shared.u64 t, %1; cvt.u32.u64 %0, t; }"
        : "=r"(a) : "l"(p));
    return a;
}
#define SWZ(o) ((o) ^ (((o) >> 3) & 0x70))

__device__ __forceinline__ void bsplit(float v, u16& h, u16& l) {
    __nv_bfloat16 bh = __float2bfloat16_rn(v);
    float r = v - __bfloat162float(bh);
    __nv_bfloat16 bl = __float2bfloat16_rn(r);
    h = __bfloat16_as_ushort(bh);
    l = __bfloat16_as_ushort(bl);
}

__device__ __forceinline__ void ldsm4(u32 addr, u32& r0, u32& r1, u32& r2, u32& r3) {
    asm volatile("ldmatrix.sync.aligned.m8n8.x4.shared.b16 {%0,%1,%2,%3}, [%4];"
                 : "=r"(r0), "=r"(r1), "=r"(r2), "=r"(r3) : "r"(addr));
}
__device__ __forceinline__ void mma16816(float* d, const u32* a, const u32* b) {
    asm volatile(
        "mma.sync.aligned.m16n8k16.row.col.f32.bf16.bf16.f32 "
        "{%0,%1,%2,%3}, {%4,%5,%6,%7}, {%8,%9}, {%0,%1,%2,%3};"
        : "+f"(d[0]), "+f"(d[1]), "+f"(d[2]), "+f"(d[3])
        : "r"(a[0]), "r"(a[1]), "r"(a[2]), "r"(a[3]), "r"(b[0]), "r"(b[1]));
}

// ------------- split_gather: fp32 strided rows -> bf16 hi/lo natural -------
__global__ void __launch_bounds__(256) split_gather_kernel(
    const float* __restrict__ src, ll sB, ll sC,
    u16* __restrict__ hi, u16* __restrict__ lo)
{
    int m = blockIdx.x;
    int k = threadIdx.x * 4;
    ll off = (ll)(m & 31) * sB + (ll)(m >> 5) * sC + k;
    float4 v = *(const float4*)(src + off);
    u16 h0, h1, h2, h3, l0, l1, l2, l3;
    bsplit(v.x, h0, l0); bsplit(v.y, h1, l1);
    bsplit(v.z, h2, l2); bsplit(v.w, h3, l3);
    ll doff = (ll)m * 1024 + k;
    *(ushort4*)(hi + doff) = make_ushort4(h0, h1, h2, h3);
    *(ushort4*)(lo + doff) = make_ushort4(l0, l1, l2, l3);
}

// ------------- transpose_split: fp32 W[k][n] -> bf16 hi/lo of W^T [n][k] ----
__global__ void __launch_bounds__(256) transpose_split_kernel(
    const float* __restrict__ src, u16* __restrict__ thi, u16* __restrict__ tlo)
{
    __shared__ float tile[32][33];
    int bx = blockIdx.x * 32;   // n
    int by = blockIdx.y * 32;   // k
    int tx = threadIdx.x & 31;
    int ty = threadIdx.x >> 5;
#pragma unroll
    for (int i = 0; i < 32; i += 8)
        tile[ty + i][tx] = src[(ll)(by + ty + i) * 1024 + bx + tx];
    __syncthreads();
#pragma unroll
    for (int i = 0; i < 32; i += 8) {
        u16 h, l;
        bsplit(tile[tx][ty + i], h, l);
        ll off = (ll)(bx + ty + i) * 1024 + (by + tx);
        thi[off] = h;
        tlo[off] = l;
    }
}

// ---------------------------------------------------------------------------
// tgemm: C[m][n] = sum_{k<1024} Af[m][k]*Bf[n][k] via bf16 split, K'=3072:
//   region0 Ahi*Bhi, region1 Alo*Bhi, region2 Ahi*Blo (per 64-wide K chunk).
// mma.sync m16n8k16 bf16, CTA 128x128, BK=64 (SW128 rows), 3-stage cp.async.
// __launch_bounds__(256,2): 2 CTAs/SM to overlap sync/load bubbles.
// Epilogue: +Add (strided/shift), fp32 out (strided b/c via &31,>>5), bf16
// hi/lo re-split (natural). All outputs nullable.
// ---------------------------------------------------------------------------
#define TG_STAGE 32768
#define TG_SMEM (3 * TG_STAGE)
#define TG_NCHK (KTOT / 64)

__global__ void __launch_bounds__(256, 2) tgemm_kernel(
    const u16* __restrict__ Ahi, const u16* __restrict__ Alo,
    const u16* __restrict__ Bhi, const u16* __restrict__ Blo,
    const float* __restrict__ Add, int adShift, ll adSB, ll adSC,
    float* __restrict__ OutF, ll ofSB, ll ofSC,
    u16* __restrict__ OBhi, u16* __restrict__ OBlo)
{
    extern __shared__ char smraw[];
    const u32 smbase = smem_u32(smraw);

    const int tid  = threadIdx.x;
    const int wid  = tid >> 5;
    const int lane = tid & 31;
    const ll mBase = (ll)blockIdx.y * 128;
    const ll nBase = (ll)blockIdx.x * 128;

    const int wm = (wid >> 1) * 32;
    const int wn = (wid & 1) * 64;

    float acc[2][8][4];
#pragma unroll
    for (int i = 0; i < 2; i++)
#pragma unroll
        for (int j = 0; j < 8; j++)
#pragma unroll
            for (int q = 0; q < 4; q++) acc[i][j][q] = 0.0f;

    auto load_chunk = [&](int c, int s) {
        const int reg = c >> 4;
        const u16* aptr = (reg == 1) ? Alo : Ahi;
        const u16* bptr = (reg == 2) ? Blo : Bhi;
        const ll kbase = (ll)(c & 15) * 64;
        u32 sa = smbase + (u32)s * TG_STAGE;
        u32 sb = sa + 16384;
#pragma unroll
        for (int i = 0; i < 4; i++) {
            int idx = i * 256 + tid;
            int row = idx >> 3;
            int cc  = (idx & 7) * 16;
            ll  kel = kbase + (idx & 7) * 8;
            asm volatile("cp.async.cg.shared.global [%0], [%1], 16;"
                :: "r"(sa + SWZ((u32)(row * 128 + cc))),
                   "l"((ull)(uintptr_t)(aptr + (mBase + row) * 1024 + kel)));
            asm volatile("cp.async.cg.shared.global [%0], [%1], 16;"
                :: "r"(sb + SWZ((u32)(row * 128 + cc))),
                   "l"((ull)(uintptr_t)(bptr + (nBase + row) * 1024 + kel)));
        }
        asm volatile("cp.async.commit_group;" ::: "memory");
    };

    load_chunk(0, 0);
    load_chunk(1, 1);

    const int aRow = (lane & 15);
    const int aKb  = (lane >> 4) * 16;
    const int bRow = (lane & 7) + ((lane >> 4) << 3);
    const int bKb  = ((lane >> 3) & 1) * 16;

#pragma unroll 1
    for (int c = 0; c < TG_NCHK; c++) {
        if (c + 2 < TG_NCHK) {
            asm volatile("cp.async.wait_group 1;" ::: "memory");
        } else {
            asm volatile("cp.async.wait_group 0;" ::: "memory");
        }
        __syncthreads();
        if (c + 2 < TG_NCHK) load_chunk(c + 2, (c + 2) % 3);

        u32 sa = smbase + (u32)(c % 3) * TG_STAGE;
        u32 sb = sa + 16384;

#pragma unroll
        for (int k16 = 0; k16 < 4; k16++) {
            const int kb = k16 * 32;
            u32 areg[2][4];
#pragma unroll
            for (int i = 0; i < 2; i++) {
                u32 ad = sa + SWZ((u32)((wm + i * 16 + aRow) * 128 + kb + aKb));
                ldsm4(ad, areg[i][0], areg[i][1], areg[i][2], areg[i][3]);
            }
            u32 breg[4][4];
#pragma unroll
            for (int j16 = 0; j16 < 4; j16++) {
                u32 bd = sb + SWZ((u32)((wn + j16 * 16 + bRow) * 128 + kb + bKb));
                ldsm4(bd, breg[j16][0], breg[j16][1], breg[j16][2], breg[j16][3]);
            }
#pragma unroll
            for (int i = 0; i < 2; i++)
#pragma unroll
                for (int j = 0; j < 8; j++)
                    mma16816(acc[i][j], areg[i], &breg[j >> 1][(j & 1) * 2]);
        }
        __syncthreads();
    }

    const int g  = lane >> 2;
    const int tg = (lane & 3) * 2;

#pragma unroll
    for (int i = 0; i < 2; i++) {
#pragma unroll
        for (int half = 0; half < 2; half++) {
            ll m = mBase + wm + i * 16 + g + half * 8;
            const float* addp = Add ?
                Add + (m & ((1 << adShift) - 1)) * adSB + (m >> adShift) * adSC + nBase
                : (const float*)0;
            float* ofp = OutF ?
                OutF + (m & 31) * ofSB + (m >> 5) * ofSC + nBase : (float*)0;
            u16* obh = OBhi ? OBhi + m * 1024 + nBase : (u16*)0;
            u16* obl = OBlo ? OBlo + m * 1024 + nBase : (u16*)0;
#pragma unroll
            for (int j = 0; j < 8; j++) {
                int n = wn + j * 8 + tg;
                float v0 = acc[i][j][half * 2 + 0];
                float v1 = acc[i][j][half * 2 + 1];
                if (addp) {
                    float2 a = *(const float2*)(addp + n);
                    v0 += a.x; v1 += a.y;
                }
                if (ofp)
                    *(float2*)(ofp + n) = make_float2(v0, v1);
                if (obh) {
                    u16 h0, h1, l0, l1;
                    bsplit(v0, h0, l0);
                    bsplit(v1, h1, l1);
                    *(ushort2*)(obh + n) = make_ushort2(h0, h1);
                    *(ushort2*)(obl + n) = make_ushort2(l0, l1);
                }
            }
        }
    }
}

// ---------------------------------------------------------------------------
// phase2: serial carry chain g[c+1] = g[c] @ R^CH + u[c]  (fp32, persistent)
// ST = S^CH = (R^CH)^T fp32 natural [n][k]. u strided from `out` rows.
// ---------------------------------------------------------------------------
__device__ __forceinline__ void ffma2(ull& d, ull a, ull b) {
    asm volatile("fma.rn.f32x2 %0, %1, %2, %0;" : "+l"(d) : "l"(a), "l"(b));
}
__device__ __forceinline__ float2 u2f2(ull v) {
    float2 f;
    f.x = __uint_as_float((unsigned)(v & 0xffffffffull));
    f.y = __uint_as_float((unsigned)(v >> 32));
    return f;
}
__device__ __forceinline__ float4 ldcg4(const float* p) {
    float4 v;
    asm volatile("ld.global.cg.v4.f32 {%0,%1,%2,%3}, [%4];"
                 : "=f"(v.x), "=f"(v.y), "=f"(v.z), "=f"(v.w) : "l"(p));
    return v;
}
#define P2_RPAD 1028
#define P2_HPAD 1032
#define P2_HS_OFF (32 * P2_RPAD)
#define P2_SMEM_FLOATS (32 * P2_RPAD + 8 * P2_HPAD)
#define P2_CTAS 128

__global__ void __launch_bounds__(256) phase2_kernel(
    const float* __restrict__ ST,
    const float* __restrict__ u, ll uSB, ll uSC,
    float* __restrict__ g, int steps)
{
    extern __shared__ float sm[];
    const int tid = threadIdx.x;
    const int col0 = (blockIdx.x & 31) * 32;
    const int b0   = (blockIdx.x >> 5) * 8;

    for (int idx = tid; idx < 32 * 1024; idx += 256) {
        int j = idx >> 10, k = idx & 1023;
        sm[j * P2_RPAD + k] = ST[(size_t)(col0 + j) * 1024 + k];
    }
    __syncthreads();

    const int j = tid & 31;
    const int b = tid >> 5;
    const float* Rrow = &sm[j * P2_RPAD];
    const float* hrow = &sm[P2_HS_OFF + b * P2_HPAD];
    const unsigned P = gridDim.x;

    for (int c = 0; c < steps; c++) {
        const float* gsrc = g + (size_t)c * (BATCH * UDIM);
        for (int i = tid; i < 2048; i += 256) {
            int bb = i >> 8, kk = (i & 255) * 4;
            float4 v = ldcg4(gsrc + (size_t)(b0 + bb) * UDIM + kk);
            *(float4*)&sm[P2_HS_OFF + bb * P2_HPAD + kk] = v;
        }
        __syncthreads();

        ull a0 = 0, a1 = 0, a2 = 0, a3 = 0;
#pragma unroll 4
        for (int k = 0; k < 1024; k += 8) {
            ulonglong2 h01 = *(const ulonglong2*)(hrow + k);
            ulonglong2 h23 = *(const ulonglong2*)(hrow + k + 4);
            ulonglong2 r01 = *(const ulonglong2*)(Rrow + k);
            ulonglong2 r23 = *(const ulonglong2*)(Rrow + k + 4);
            ffma2(a0, h01.x, r01.x); ffma2(a1, h01.y, r01.y);
            ffma2(a2, h23.x, r23.x); ffma2(a3, h23.y, r23.y);
        }
        float2 f0 = u2f2(a0), f1 = u2f2(a1), f2 = u2f2(a2), f3 = u2f2(a3);
        float sum = ((f0.x + f0.y) + (f1.x + f1.y)) +
                    ((f2.x + f2.y) + (f3.x + f3.y));

        float uv = __ldg(u + (ll)(b0 + b) * uSB + (ll)c * uSC + col0 + j);
        g[(size_t)(c + 1) * (BATCH * UDIM) + (size_t)(b0 + b) * UDIM + col0 + j] =
            sum + uv;

        __threadfence();
        __syncthreads();
        if (tid == 0) {
            unsigned arrived = atomicAdd((unsigned*)&g_bar[c], 1u) + 1u;
            if (arrived < P)
                while (g_bar[c] < P) __nanosleep(64);
            __threadfence();
        }
        __syncthreads();
    }
}

// ---------------------------------------------------------------------------
extern "C" void kernel_launch(void* const* d_in, const int* in_sizes, int n_in,
                              void* d_out, int out_size)
{
    const float* x    = (const float*)d_in[0];
    const float* h0   = (const float*)d_in[1];
    const float* cst  = (const float*)d_in[2];
    const float* kern = (const float*)d_in[3];
    const float* rker = (const float*)d_in[4];
    float* out = (float*)d_out;

    const ll TU = (ll)TDIM * UDIM;   // out stride per batch
    const ll CU = (ll)CH * UDIM;     // out stride per chunk (16 rows)
    const ll SL = (ll)UDIM * UDIM;   // power-slot stride

    u16 *Xhi, *Xlo, *UAhi, *UAlo, *UBhi, *UBlo, *KThi, *KTlo;
    u16 *SPhi, *SPlo, *RPhi, *RPlo;
    float *PowF, *gbuf;
    cudaGetSymbolAddress((void**)&Xhi, g_Xhi);   cudaGetSymbolAddress((void**)&Xlo, g_Xlo);
    cudaGetSymbolAddress((void**)&UAhi, g_UAhi); cudaGetSymbolAddress((void**)&UAlo, g_UAlo);
    cudaGetSymbolAddress((void**)&UBhi, g_UBhi); cudaGetSymbolAddress((void**)&UBlo, g_UBlo);
    cudaGetSymbolAddress((void**)&KThi, g_KThi); cudaGetSymbolAddress((void**)&KTlo, g_KTlo);
    cudaGetSymbolAddress((void**)&SPhi, g_SPhi); cudaGetSymbolAddress((void**)&SPlo, g_SPlo);
    cudaGetSymbolAddress((void**)&RPhi, g_RPhi); cudaGetSymbolAddress((void**)&RPlo, g_RPlo);
    cudaGetSymbolAddress((void**)&PowF, g_PowF);
    cudaGetSymbolAddress((void**)&gbuf, g_gbuf);

    cudaFuncSetAttribute(tgemm_kernel,
        cudaFuncAttributeMaxDynamicSharedMemorySize, TG_SMEM);
    cudaFuncSetAttribute(phase2_kernel,
        cudaFuncAttributeMaxDynamicSharedMemorySize, P2_SMEM_FLOATS * 4);

    bar_reset_kernel<<<(MAX_BAR + 255) / 256, 256>>>();

    // input splits
    split_gather_kernel<<<BATCH * TDIM, 256>>>(x, 1024, 32768, Xhi, Xlo);
    dim3 gt(32, 32);
    transpose_split_kernel<<<gt, 256>>>(kern, KThi, KTlo);
    transpose_split_kernel<<<gt, 256>>>(rker, SPhi, SPlo);             // S^1
    split_gather_kernel<<<UDIM, 256>>>(rker, 1024, 32768, RPhi, RPlo); // R^1
    copy_h0_kernel<<<(BATCH * UDIM + 255) / 256, 256>>>(h0, gbuf);

    // phase 0: xw = x @ kernel + const -> out (rows m = b*T + t)
    {
        dim3 g0(8, 512);
        tgemm_kernel<<<g0, 256, TG_SMEM>>>(Xhi, Xlo, KThi, KTlo,
            cst, 11, 0, 1024,
            out, 1024, 32768,
            nullptr, nullptr);
    }

    // power chain (log depth): S^{a+b} = S^a x (B=R^b); R^{a+b} = R^a x (B=S^b)
    {
        dim3 g1(8, 8), g2(8, 16), g4(8, 32), g8(8, 64);
        // S^2 -> SP slot 1
        tgemm_kernel<<<g1, 256, TG_SMEM>>>(SPhi, SPlo, RPhi, RPlo,
            nullptr, 5, 0, 0, nullptr, 0, 0, SPhi + SL, SPlo + SL);
        // R^2 -> RP slot 1
        tgemm_kernel<<<g1, 256, TG_SMEM>>>(RPhi, RPlo, SPhi, SPlo,
            nullptr, 5, 0, 0, nullptr, 0, 0, RPhi + SL, RPlo + SL);
        // S^3,S^4 = [S^1,S^2] x R^2 -> SP slots 2,3
        tgemm_kernel<<<g2, 256, TG_SMEM>>>(SPhi, SPlo, RPhi + SL, RPlo + SL,
            nullptr, 5, 0, 0, nullptr, 0, 0, SPhi + 2 * SL, SPlo + 2 * SL);
        // R^4 -> RP slot 2
        tgemm_kernel<<<g1, 256, TG_SMEM>>>(RPhi + SL, RPlo + SL, SPhi + SL, SPlo + SL,
            nullptr, 5, 0, 0, nullptr, 0, 0, RPhi + 2 * SL, RPlo + 2 * SL);
        // S^5..S^8 = [S^1..S^4] x R^4 -> SP slots 4..7
        tgemm_kernel<<<g4, 256, TG_SMEM>>>(SPhi, SPlo, RPhi + 2 * SL, RPlo + 2 * SL,
            nullptr, 5, 0, 0, nullptr, 0, 0, SPhi + 4 * SL, SPlo + 4 * SL);
        // R^8 = R^4 x S^4 -> RP slot 3
        tgemm_kernel<<<g1, 256, TG_SMEM>>>(RPhi + 2 * SL, RPlo + 2 * SL,
            SPhi + 3 * SL, SPlo + 3 * SL,
            nullptr, 5, 0, 0, nullptr, 0, 0, RPhi + 3 * SL, RPlo + 3 * SL);
        // S^9..S^16 = [S^1..S^8] x R^8 -> SP slots 8..15, fp32 -> PowF
        tgemm_kernel<<<g8, 256, TG_SMEM>>>(SPhi, SPlo, RPhi + 3 * SL, RPlo + 3 * SL,
            nullptr, 5, 0, 0, PowF, 1024, 32768, SPhi + 8 * SL, SPlo + 8 * SL);
    }

    // gather xw rows at t = c*CH (chunk heads), split -> UA  (m = c*32+b)
    split_gather_kernel<<<NCH * BATCH, 256>>>(out, TU, CU, UAhi, UAlo);

    // phase 1: Horner u_j = u_{j-1} @ R + xw_{c*CH+j}, j = 1..CH-1.
    // Writes u_j fp32 into out rows t = c*CH+j (prefix values) and bf16
    // split for the next step (except last).
    {
        dim3 gp(8, 32);   // M = 4096
        for (int jj = 1; jj < CH; jj++) {
            const u16* ah = (jj & 1) ? UAhi : UBhi;
            const u16* al = (jj & 1) ? UAlo : UBlo;
            u16* oh = (jj & 1) ? UBhi : UAhi;
            u16* ol = (jj & 1) ? UBlo : UAlo;
            bool last = (jj == CH - 1);
            tgemm_kernel<<<gp, 256, TG_SMEM>>>(ah, al, SPhi, SPlo,
                out + (size_t)jj * UDIM, 5, TU, CU,
                out + (size_t)jj * UDIM, TU, CU,
                last ? nullptr : oh, last ? nullptr : ol);
        }
    }

    // phase 2: g[c+1] = g[c] @ R^CH + u_{CH-1,c}  (127 serial steps)
    // S^16 fp32 = PowF rows 7168..8191; u from out rows t = c*CH + 15.
    phase2_kernel<<<P2_CTAS, 256, P2_SMEM_FLOATS * 4>>>(
        PowF + (size_t)7168 * 1024,
        out + (size_t)(CH - 1) * UDIM, TU, CU,
        gbuf, NCH - 1);

    // split carries -> UA  (m = c*32+b)
    split_gather_kernel<<<NCH * BATCH, 256>>>(gbuf, 1024, 32768, UAhi, UAlo);

    // phase 3 (single GEMM): out_{c*CH+j} += g_c @ R^{j+1} for all j at once.
    // A = g split (M = 4096), B = stacked S^1..S^16 (N = 16384); N maps
    // contiguously into out: offset = b*TU + c*CU + n.
    {
        dim3 gp(CH * 1024 / 128, 32);   // (128, 32) = 4096 CTAs
        tgemm_kernel<<<gp, 256, TG_SMEM>>>(UAhi, UAlo, SPhi, SPlo,
            out, 5, TU, CU,
            out, TU, CU,
            nullptr, nullptr);
    }
}

// round 8
// speedup vs baseline: 1.3340x; 1.1249x over previous
#include <cuda_runtime.h>
#include <cuda_bf16.h>
#include <cstdint>

typedef unsigned long long ull;
typedef long long ll;
typedef unsigned short u16;
typedef unsigned int u32;

#define UDIM 1024
#define BATCH 32
#define TDIM 2048
#define CH 16
#define NCH (TDIM / CH)          // 128
#define KTOT 3072

// ---------------- scratch (device globals; no runtime alloc) ----------------
__device__ u16   g_Xhi[(size_t)BATCH * TDIM * UDIM];
__device__ u16   g_Xlo[(size_t)BATCH * TDIM * UDIM];
__device__ u16   g_UAhi[NCH * BATCH * UDIM], g_UAlo[NCH * BATCH * UDIM];
__device__ u16   g_UBhi[NCH * BATCH * UDIM], g_UBlo[NCH * BATCH * UDIM];
__device__ u16   g_KThi[UDIM * UDIM], g_KTlo[UDIM * UDIM];
__device__ u16   g_SPhi[CH * UDIM * UDIM], g_SPlo[CH * UDIM * UDIM];  // S^1..S^16
__device__ u16   g_S32hi[UDIM * UDIM], g_S32lo[UDIM * UDIM];          // S^32
__device__ u16   g_RPhi[6 * UDIM * UDIM], g_RPlo[6 * UDIM * UDIM];    // R^1,2,4,8,16,32
__device__ float g_W4F[UDIM * UDIM];        // S^64 fp32 (for serial chain)
__device__ float g_sP1[64 * BATCH * UDIM];  // s' level-1 combines (8MB)
__device__ float g_sP2[32 * BATCH * UDIM];  // s'' level-2 combines (4MB)
__device__ float g_gbuf[NCH * BATCH * UDIM];

#define MAX_BAR 2048
__device__ volatile unsigned g_bar[MAX_BAR];

__global__ void __launch_bounds__(256) bar_reset_kernel() {
    int i = blockIdx.x * blockDim.x + threadIdx.x;
    if (i < MAX_BAR) *(unsigned*)&g_bar[i] = 0u;
}
__global__ void __launch_bounds__(256) copy_h0_kernel(const float* __restrict__ h0,
                                                      float* __restrict__ g) {
    int i = blockIdx.x * blockDim.x + threadIdx.x;
    if (i < BATCH * UDIM) g[i] = h0[i];
}

// ---------------- helpers ----------------
__device__ __forceinline__ u32 smem_u32(const void* p) {
    u32 a;
    asm("{ .reg .u64 t; cvta.to.shared.u64 t, %1; cvt.u32.u64 %0, t; }"
        : "=r"(a) : "l"(p));
    return a;
}
#define SWZ(o) ((o) ^ (((o) >> 3) & 0x70))

__device__ __forceinline__ void bsplit(float v, u16& h, u16& l) {
    __nv_bfloat16 bh = __float2bfloat16_rn(v);
    float r = v - __bfloat162float(bh);
    __nv_bfloat16 bl = __float2bfloat16_rn(r);
    h = __bfloat16_as_ushort(bh);
    l = __bfloat16_as_ushort(bl);
}

__device__ __forceinline__ void ldsm4(u32 addr, u32& r0, u32& r1, u32& r2, u32& r3) {
    asm volatile("ldmatrix.sync.aligned.m8n8.x4.shared.b16 {%0,%1,%2,%3}, [%4];"
                 : "=r"(r0), "=r"(r1), "=r"(r2), "=r"(r3) : "r"(addr));
}
__device__ __forceinline__ void mma16816(float* d, const u32* a, const u32* b) {
    asm volatile(
        "mma.sync.aligned.m16n8k16.row.col.f32.bf16.bf16.f32 "
        "{%0,%1,%2,%3}, {%4,%5,%6,%7}, {%8,%9}, {%0,%1,%2,%3};"
        : "+f"(d[0]), "+f"(d[1]), "+f"(d[2]), "+f"(d[3])
        : "r"(a[0]), "r"(a[1]), "r"(a[2]), "r"(a[3]), "r"(b[0]), "r"(b[1]));
}

// ------------- split_gather: fp32 strided rows -> bf16 hi/lo natural -------
__global__ void __launch_bounds__(256) split_gather_kernel(
    const float* __restrict__ src, ll sB, ll sC,
    u16* __restrict__ hi, u16* __restrict__ lo)
{
    int m = blockIdx.x;
    int k = threadIdx.x * 4;
    ll off = (ll)(m & 31) * sB + (ll)(m >> 5) * sC + k;
    float4 v = *(const float4*)(src + off);
    u16 h0, h1, h2, h3, l0, l1, l2, l3;
    bsplit(v.x, h0, l0); bsplit(v.y, h1, l1);
    bsplit(v.z, h2, l2); bsplit(v.w, h3, l3);
    ll doff = (ll)m * 1024 + k;
    *(ushort4*)(hi + doff) = make_ushort4(h0, h1, h2, h3);
    *(ushort4*)(lo + doff) = make_ushort4(l0, l1, l2, l3);
}

// ------------- transpose_split: fp32 W[k][n] -> bf16 hi/lo of W^T [n][k] ----
__global__ void __launch_bounds__(256) transpose_split_kernel(
    const float* __restrict__ src, u16* __restrict__ thi, u16* __restrict__ tlo)
{
    __shared__ float tile[32][33];
    int bx = blockIdx.x * 32;   // n
    int by = blockIdx.y * 32;   // k
    int tx = threadIdx.x & 31;
    int ty = threadIdx.x >> 5;
#pragma unroll
    for (int i = 0; i < 32; i += 8)
        tile[ty + i][tx] = src[(ll)(by + ty + i) * 1024 + bx + tx];
    __syncthreads();
#pragma unroll
    for (int i = 0; i < 32; i += 8) {
        u16 h, l;
        bsplit(tile[tx][ty + i], h, l);
        ll off = (ll)(bx + ty + i) * 1024 + (by + tx);
        thi[off] = h;
        tlo[off] = l;
    }
}

// ---------------------------------------------------------------------------
// tgemm: C[m][n] = sum_{k<1024} Af[m][k]*Bf[n][k] via bf16 split, K'=3072:
//   region0 Ahi*Bhi, region1 Alo*Bhi, region2 Ahi*Blo (per 64-wide K chunk).
// mma.sync m16n8k16 bf16, CTA 128x128, BK=64 (SW128 rows), 3-stage cp.async.
// Epilogue: +Add (strided/shift), fp32 out (strided b/c via &31,>>5), bf16
// hi/lo re-split (natural). All outputs nullable.
// ---------------------------------------------------------------------------
#define TG_STAGE 32768
#define TG_SMEM (3 * TG_STAGE)
#define TG_NCHK (KTOT / 64)

__global__ void __launch_bounds__(256, 2) tgemm_kernel(
    const u16* __restrict__ Ahi, const u16* __restrict__ Alo,
    const u16* __restrict__ Bhi, const u16* __restrict__ Blo,
    const float* __restrict__ Add, int adShift, ll adSB, ll adSC,
    float* __restrict__ OutF, ll ofSB, ll ofSC,
    u16* __restrict__ OBhi, u16* __restrict__ OBlo)
{
    extern __shared__ char smraw[];
    const u32 smbase = smem_u32(smraw);

    const int tid  = threadIdx.x;
    const int wid  = tid >> 5;
    const int lane = tid & 31;
    const ll mBase = (ll)blockIdx.y * 128;
    const ll nBase = (ll)blockIdx.x * 128;

    const int wm = (wid >> 1) * 32;
    const int wn = (wid & 1) * 64;

    float acc[2][8][4];
#pragma unroll
    for (int i = 0; i < 2; i++)
#pragma unroll
        for (int j = 0; j < 8; j++)
#pragma unroll
            for (int q = 0; q < 4; q++) acc[i][j][q] = 0.0f;

    auto load_chunk = [&](int c, int s) {
        const int reg = c >> 4;
        const u16* aptr = (reg == 1) ? Alo : Ahi;
        const u16* bptr = (reg == 2) ? Blo : Bhi;
        const ll kbase = (ll)(c & 15) * 64;
        u32 sa = smbase + (u32)s * TG_STAGE;
        u32 sb = sa + 16384;
#pragma unroll
        for (int i = 0; i < 4; i++) {
            int idx = i * 256 + tid;
            int row = idx >> 3;
            int cc  = (idx & 7) * 16;
            ll  kel = kbase + (idx & 7) * 8;
            asm volatile("cp.async.cg.shared.global [%0], [%1], 16;"
                :: "r"(sa + SWZ((u32)(row * 128 + cc))),
                   "l"((ull)(uintptr_t)(aptr + (mBase + row) * 1024 + kel)));
            asm volatile("cp.async.cg.shared.global [%0], [%1], 16;"
                :: "r"(sb + SWZ((u32)(row * 128 + cc))),
                   "l"((ull)(uintptr_t)(bptr + (nBase + row) * 1024 + kel)));
        }
        asm volatile("cp.async.commit_group;" ::: "memory");
    };

    load_chunk(0, 0);
    load_chunk(1, 1);

    const int aRow = (lane & 15);
    const int aKb  = (lane >> 4) * 16;
    const int bRow = (lane & 7) + ((lane >> 4) << 3);
    const int bKb  = ((lane >> 3) & 1) * 16;

#pragma unroll 1
    for (int c = 0; c < TG_NCHK; c++) {
        if (c + 2 < TG_NCHK) {
            asm volatile("cp.async.wait_group 1;" ::: "memory");
        } else {
            asm volatile("cp.async.wait_group 0;" ::: "memory");
        }
        __syncthreads();
        if (c + 2 < TG_NCHK) load_chunk(c + 2, (c + 2) % 3);

        u32 sa = smbase + (u32)(c % 3) * TG_STAGE;
        u32 sb = sa + 16384;

#pragma unroll
        for (int k16 = 0; k16 < 4; k16++) {
            const int kb = k16 * 32;
            u32 areg[2][4];
#pragma unroll
            for (int i = 0; i < 2; i++) {
                u32 ad = sa + SWZ((u32)((wm + i * 16 + aRow) * 128 + kb + aKb));
                ldsm4(ad, areg[i][0], areg[i][1], areg[i][2], areg[i][3]);
            }
            u32 breg[4][4];
#pragma unroll
            for (int j16 = 0; j16 < 4; j16++) {
                u32 bd = sb + SWZ((u32)((wn + j16 * 16 + bRow) * 128 + kb + bKb));
                ldsm4(bd, breg[j16][0], breg[j16][1], breg[j16][2], breg[j16][3]);
            }
#pragma unroll
            for (int i = 0; i < 2; i++)
#pragma unroll
                for (int j = 0; j < 8; j++)
                    mma16816(acc[i][j], areg[i], &breg[j >> 1][(j & 1) * 2]);
        }
        __syncthreads();
    }

    const int g  = lane >> 2;
    const int tg = (lane & 3) * 2;

#pragma unroll
    for (int i = 0; i < 2; i++) {
#pragma unroll
        for (int half = 0; half < 2; half++) {
            ll m = mBase + wm + i * 16 + g + half * 8;
            const float* addp = Add ?
                Add + (m & ((1 << adShift) - 1)) * adSB + (m >> adShift) * adSC + nBase
                : (const float*)0;
            float* ofp = OutF ?
                OutF + (m & 31) * ofSB + (m >> 5) * ofSC + nBase : (float*)0;
            u16* obh = OBhi ? OBhi + m * 1024 + nBase : (u16*)0;
            u16* obl = OBlo ? OBlo + m * 1024 + nBase : (u16*)0;
#pragma unroll
            for (int j = 0; j < 8; j++) {
                int n = wn + j * 8 + tg;
                float v0 = acc[i][j][half * 2 + 0];
                float v1 = acc[i][j][half * 2 + 1];
                if (addp) {
                    float2 a = *(const float2*)(addp + n);
                    v0 += a.x; v1 += a.y;
                }
                if (ofp)
                    *(float2*)(ofp + n) = make_float2(v0, v1);
                if (obh) {
                    u16 h0, h1, l0, l1;
                    bsplit(v0, h0, l0);
                    bsplit(v1, h1, l1);
                    *(ushort2*)(obh + n) = make_ushort2(h0, h1);
                    *(ushort2*)(obl + n) = make_ushort2(l0, l1);
                }
            }
        }
    }
}

// ---------------------------------------------------------------------------
// phase2: serial carry chain G[e+1] = G[e] @ W + u[e]  (fp32, persistent)
// ST = W^T fp32 natural [n][k]; G states gStep elements apart in g.
// ---------------------------------------------------------------------------
__device__ __forceinline__ void ffma2(ull& d, ull a, ull b) {
    asm volatile("fma.rn.f32x2 %0, %1, %2, %0;" : "+l"(d) : "l"(a), "l"(b));
}
__device__ __forceinline__ float2 u2f2(ull v) {
    float2 f;
    f.x = __uint_as_float((unsigned)(v & 0xffffffffull));
    f.y = __uint_as_float((unsigned)(v >> 32));
    return f;
}
__device__ __forceinline__ float4 ldcg4(const float* p) {
    float4 v;
    asm volatile("ld.global.cg.v4.f32 {%0,%1,%2,%3}, [%4];"
                 : "=f"(v.x), "=f"(v.y), "=f"(v.z), "=f"(v.w) : "l"(p));
    return v;
}
#define P2_RPAD 1028
#define P2_HPAD 1032
#define P2_HS_OFF (32 * P2_RPAD)
#define P2_SMEM_FLOATS (32 * P2_RPAD + 8 * P2_HPAD)
#define P2_CTAS 128

__global__ void __launch_bounds__(256) phase2_kernel(
    const float* __restrict__ ST,
    const float* __restrict__ u, ll uSB, ll uSC,
    float* __restrict__ g, ll gStep, int steps)
{
    extern __shared__ float sm[];
    const int tid = threadIdx.x;
    const int col0 = (blockIdx.x & 31) * 32;
    const int b0   = (blockIdx.x >> 5) * 8;

    for (int idx = tid; idx < 32 * 1024; idx += 256) {
        int j = idx >> 10, k = idx & 1023;
        sm[j * P2_RPAD + k] = ST[(size_t)(col0 + j) * 1024 + k];
    }
    __syncthreads();

    const int j = tid & 31;
    const int b = tid >> 5;
    const float* Rrow = &sm[j * P2_RPAD];
    const float* hrow = &sm[P2_HS_OFF + b * P2_HPAD];
    const unsigned P = gridDim.x;

    for (int c = 0; c < steps; c++) {
        const float* gsrc = g + (ll)c * gStep;
        for (int i = tid; i < 2048; i += 256) {
            int bb = i >> 8, kk = (i & 255) * 4;
            float4 v = ldcg4(gsrc + (size_t)(b0 + bb) * UDIM + kk);
            *(float4*)&sm[P2_HS_OFF + bb * P2_HPAD + kk] = v;
        }
        __syncthreads();

        ull a0 = 0, a1 = 0, a2 = 0, a3 = 0;
#pragma unroll 4
        for (int k = 0; k < 1024; k += 8) {
            ulonglong2 h01 = *(const ulonglong2*)(hrow + k);
            ulonglong2 h23 = *(const ulonglong2*)(hrow + k + 4);
            ulonglong2 r01 = *(const ulonglong2*)(Rrow + k);
            ulonglong2 r23 = *(const ulonglong2*)(Rrow + k + 4);
            ffma2(a0, h01.x, r01.x); ffma2(a1, h01.y, r01.y);
            ffma2(a2, h23.x, r23.x); ffma2(a3, h23.y, r23.y);
        }
        float2 f0 = u2f2(a0), f1 = u2f2(a1), f2 = u2f2(a2), f3 = u2f2(a3);
        float sum = ((f0.x + f0.y) + (f1.x + f1.y)) +
                    ((f2.x + f2.y) + (f3.x + f3.y));

        float uv = __ldg(u + (ll)(b0 + b) * uSB + (ll)c * uSC + col0 + j);
        g[(ll)(c + 1) * gStep + (size_t)(b0 + b) * UDIM + col0 + j] = sum + uv;

        __threadfence();
        __syncthreads();
        if (tid == 0) {
            unsigned arrived = atomicAdd((unsigned*)&g_bar[c], 1u) + 1u;
            if (arrived < P) {
                while (g_bar[c] < P) { }   // tight spin: wake latency matters
            }
            __threadfence();
        }
        __syncthreads();
    }
}

// ---------------------------------------------------------------------------
extern "C" void kernel_launch(void* const* d_in, const int* in_sizes, int n_in,
                              void* d_out, int out_size)
{
    const float* x    = (const float*)d_in[0];
    const float* h0   = (const float*)d_in[1];
    const float* cst  = (const float*)d_in[2];
    const float* kern = (const float*)d_in[3];
    const float* rker = (const float*)d_in[4];
    float* out = (float*)d_out;

    const ll TU = (ll)TDIM * UDIM;   // out stride per batch
    const ll CU = (ll)CH * UDIM;     // out stride per chunk (16 rows)
    const ll SL = (ll)UDIM * UDIM;   // power-slot stride
    const ll GB = (ll)BATCH * UDIM;  // one carry state (32x1024)

    u16 *Xhi, *Xlo, *UAhi, *UAlo, *UBhi, *UBlo, *KThi, *KTlo;
    u16 *SPhi, *SPlo, *RPhi, *RPlo, *S32hi, *S32lo;
    float *W4F, *sP1, *sP2, *gbuf;
    cudaGetSymbolAddress((void**)&Xhi, g_Xhi);   cudaGetSymbolAddress((void**)&Xlo, g_Xlo);
    cudaGetSymbolAddress((void**)&UAhi, g_UAhi); cudaGetSymbolAddress((void**)&UAlo, g_UAlo);
    cudaGetSymbolAddress((void**)&UBhi, g_UBhi); cudaGetSymbolAddress((void**)&UBlo, g_UBlo);
    cudaGetSymbolAddress((void**)&KThi, g_KThi); cudaGetSymbolAddress((void**)&KTlo, g_KTlo);
    cudaGetSymbolAddress((void**)&SPhi, g_SPhi); cudaGetSymbolAddress((void**)&SPlo, g_SPlo);
    cudaGetSymbolAddress((void**)&RPhi, g_RPhi); cudaGetSymbolAddress((void**)&RPlo, g_RPlo);
    cudaGetSymbolAddress((void**)&S32hi, g_S32hi); cudaGetSymbolAddress((void**)&S32lo, g_S32lo);
    cudaGetSymbolAddress((void**)&W4F, g_W4F);
    cudaGetSymbolAddress((void**)&sP1, g_sP1);
    cudaGetSymbolAddress((void**)&sP2, g_sP2);
    cudaGetSymbolAddress((void**)&gbuf, g_gbuf);

    cudaFuncSetAttribute(tgemm_kernel,
        cudaFuncAttributeMaxDynamicSharedMemorySize, TG_SMEM);
    cudaFuncSetAttribute(phase2_kernel,
        cudaFuncAttributeMaxDynamicSharedMemorySize, P2_SMEM_FLOATS * 4);

    bar_reset_kernel<<<(MAX_BAR + 255) / 256, 256>>>();

    // input splits
    split_gather_kernel<<<BATCH * TDIM, 256>>>(x, 1024, 32768, Xhi, Xlo);
    dim3 gt(32, 32);
    transpose_split_kernel<<<gt, 256>>>(kern, KThi, KTlo);
    transpose_split_kernel<<<gt, 256>>>(rker, SPhi, SPlo);             // S^1
    split_gather_kernel<<<UDIM, 256>>>(rker, 1024, 32768, RPhi, RPlo); // R^1
    copy_h0_kernel<<<(BATCH * UDIM + 255) / 256, 256>>>(h0, gbuf);

    // phase 0: xw = x @ kernel + const -> out (rows m = b*T + t)
    {
        dim3 g0(8, 512);
        tgemm_kernel<<<g0, 256, TG_SMEM>>>(Xhi, Xlo, KThi, KTlo,
            cst, 11, 0, 1024,
            out, 1024, 32768,
            nullptr, nullptr);
    }

    // power chain (log depth): S^{a+b} = S^a x (B=R^b); R^{a+b} = R^a x (B=S^b)
    {
        dim3 g1(8, 8), g2(8, 16), g4(8, 32), g8(8, 64);
        tgemm_kernel<<<g1, 256, TG_SMEM>>>(SPhi, SPlo, RPhi, RPlo,            // S^2
            nullptr, 5, 0, 0, nullptr, 0, 0, SPhi + SL, SPlo + SL);
        tgemm_kernel<<<g1, 256, TG_SMEM>>>(RPhi, RPlo, SPhi, SPlo,            // R^2
            nullptr, 5, 0, 0, nullptr, 0, 0, RPhi + SL, RPlo + SL);
        tgemm_kernel<<<g2, 256, TG_SMEM>>>(SPhi, SPlo, RPhi + SL, RPlo + SL,  // S^3,4
            nullptr, 5, 0, 0, nullptr, 0, 0, SPhi + 2 * SL, SPlo + 2 * SL);
        tgemm_kernel<<<g1, 256, TG_SMEM>>>(RPhi + SL, RPlo + SL,              // R^4
            SPhi + SL, SPlo + SL,
            nullptr, 5, 0, 0, nullptr, 0, 0, RPhi + 2 * SL, RPlo + 2 * SL);
        tgemm_kernel<<<g4, 256, TG_SMEM>>>(SPhi, SPlo,                        // S^5..8
            RPhi + 2 * SL, RPlo + 2 * SL,
            nullptr, 5, 0, 0, nullptr, 0, 0, SPhi + 4 * SL, SPlo + 4 * SL);
        tgemm_kernel<<<g1, 256, TG_SMEM>>>(RPhi + 2 * SL, RPlo + 2 * SL,      // R^8
            SPhi + 3 * SL, SPlo + 3 * SL,
            nullptr, 5, 0, 0, nullptr, 0, 0, RPhi + 3 * SL, RPlo + 3 * SL);
        tgemm_kernel<<<g8, 256, TG_SMEM>>>(SPhi, SPlo,                        // S^9..16
            RPhi + 3 * SL, RPlo + 3 * SL,
            nullptr, 5, 0, 0, nullptr, 0, 0, SPhi + 8 * SL, SPlo + 8 * SL);
        tgemm_kernel<<<g1, 256, TG_SMEM>>>(RPhi + 3 * SL, RPlo + 3 * SL,      // R^16
            SPhi + 7 * SL, SPlo + 7 * SL,
            nullptr, 5, 0, 0, nullptr, 0, 0, RPhi + 4 * SL, RPlo + 4 * SL);
        tgemm_kernel<<<g1, 256, TG_SMEM>>>(RPhi + 4 * SL, RPlo + 4 * SL,      // R^32
            SPhi + 15 * SL, SPlo + 15 * SL,
            nullptr, 5, 0, 0, nullptr, 0, 0, RPhi + 5 * SL, RPlo + 5 * SL);
        tgemm_kernel<<<g1, 256, TG_SMEM>>>(SPhi + 15 * SL, SPlo + 15 * SL,    // S^32
            RPhi + 4 * SL, RPlo + 4 * SL,
            nullptr, 5, 0, 0, nullptr, 0, 0, S32hi, S32lo);
        tgemm_kernel<<<g1, 256, TG_SMEM>>>(S32hi, S32lo,                      // S^64 fp32
            RPhi + 5 * SL, RPlo + 5 * SL,
            nullptr, 5, 0, 0, W4F, 1024, 32768, nullptr, nullptr);
    }

    // gather xw rows at t = c*CH (chunk heads), split -> UA  (m = c*32+b)
    split_gather_kernel<<<NCH * BATCH, 256>>>(out, TU, CU, UAhi, UAlo);

    // phase 1: Horner u_j = u_{j-1} @ R + xw_{c*CH+j}, j = 1..CH-1.
    // Writes u_j fp32 into out rows t = c*CH+j (prefix values) and bf16
    // split for the next step (except last). s_c = u_{15,c} lands in out.
    {
        dim3 gp(8, 32);   // M = 4096
        for (int jj = 1; jj < CH; jj++) {
            const u16* ah = (jj & 1) ? UAhi : UBhi;
            const u16* al = (jj & 1) ? UAlo : UBlo;
            u16* oh = (jj & 1) ? UBhi : UAhi;
            u16* ol = (jj & 1) ? UBlo : UAlo;
            bool last = (jj == CH - 1);
            tgemm_kernel<<<gp, 256, TG_SMEM>>>(ah, al, SPhi, SPlo,
                out + (size_t)jj * UDIM, 5, TU, CU,
                out + (size_t)jj * UDIM, TU, CU,
                last ? nullptr : oh, last ? nullptr : ol);
        }
    }

    // ---- phase 2 (radix-4 reduced): chain g_{c+1} = g_c W + s_c, W = R^16 ----
    const float* sBase = out + (size_t)(CH - 1) * UDIM;  // s_c at t = c*16+15

    // combine1: s'_d = s_{2d} W + s_{2d+1}  (d = 0..63, M = 2048)
    split_gather_kernel<<<2048, 256>>>(sBase, TU, 2 * CU, UBhi, UBlo);
    {
        dim3 gp(8, 16);
        tgemm_kernel<<<gp, 256, TG_SMEM>>>(UBhi, UBlo,
            SPhi + 15 * SL, SPlo + 15 * SL,                 // B = S^16
            sBase + CU, 5, TU, 2 * CU,                      // + s_{2d+1}
            sP1, 1024, 32768,
            nullptr, nullptr);
    }
    // combine2: s''_e = s'_{2e} W^2 + s'_{2e+1}  (e = 0..31, M = 1024)
    split_gather_kernel<<<1024, 256>>>(sP1, 1024, 2 * 32768, UBhi, UBlo);
    {
        dim3 gp(8, 8);
        tgemm_kernel<<<gp, 256, TG_SMEM>>>(UBhi, UBlo, S32hi, S32lo,
            sP1 + 32768, 5, 1024, 2 * 32768,
            sP2, 1024, 32768,
            nullptr, nullptr);
    }
    // serial chain (31 steps): g_{4(e+1)} = g_{4e} W^4 + s''_e
    phase2_kernel<<<P2_CTAS, 256, P2_SMEM_FLOATS * 4>>>(
        W4F, sP2, 1024, 32768, gbuf, 4 * GB, 32 - 1);
    // backfill2: g_{4e+2} = g_{4e} W^2 + s'_{2e}  (e = 0..31, M = 1024)
    split_gather_kernel<<<1024, 256>>>(gbuf, 1024, 4 * 32768, UBhi, UBlo);
    {
        dim3 gp(8, 8);
        tgemm_kernel<<<gp, 256, TG_SMEM>>>(UBhi, UBlo, S32hi, S32lo,
            sP1, 5, 1024, 2 * 32768,
            gbuf + 2 * GB, 1024, 4 * 32768,
            nullptr, nullptr);
    }
    // backfill1: g_{2d+1} = g_{2d} W + s_{2d}  (d = 0..63, M = 2048)
    split_gather_kernel<<<2048, 256>>>(gbuf, 1024, 2 * 32768, UBhi, UBlo);
    {
        dim3 gp(8, 16);
        tgemm_kernel<<<gp, 256, TG_SMEM>>>(UBhi, UBlo,
            SPhi + 15 * SL, SPlo + 15 * SL,
            sBase, 5, TU, 2 * CU,
            gbuf + GB, 1024, 2 * 32768,
            nullptr, nullptr);
    }

    // split all carries -> UA  (m = c*32+b)
    split_gather_kernel<<<NCH * BATCH, 256>>>(gbuf, 1024, 32768, UAhi, UAlo);

    // phase 3 (single GEMM): out_{c*CH+j} += g_c @ R^{j+1} for all j at once.
    {
        dim3 gp(CH * 1024 / 128, 32);   // (128, 32) = 4096 CTAs
        tgemm_kernel<<<gp, 256, TG_SMEM>>>(UAhi, UAlo, SPhi, SPlo,
            out, 5, TU, CU,
            out, TU, CU,
            nullptr, nullptr);
    }
}

// round 9
// speedup vs baseline: 1.4603x; 1.0947x over previous
#include <cuda_runtime.h>
#include <cuda_bf16.h>
#include <cstdint>

typedef unsigned long long ull;
typedef long long ll;
typedef unsigned short u16;
typedef unsigned int u32;

#define UDIM 1024
#define BATCH 32
#define TDIM 2048
#define CH 16
#define NCH (TDIM / CH)          // 128
#define KTOT 3072

// ---------------- scratch (device globals; no runtime alloc) ----------------
__device__ u16   g_Xhi[(size_t)BATCH * TDIM * UDIM];
__device__ u16   g_Xlo[(size_t)BATCH * TDIM * UDIM];
__device__ u16   g_UAhi[NCH * BATCH * UDIM], g_UAlo[NCH * BATCH * UDIM];
__device__ u16   g_UBhi[NCH * BATCH * UDIM], g_UBlo[NCH * BATCH * UDIM];
__device__ u16   g_KThi[UDIM * UDIM], g_KTlo[UDIM * UDIM];
__device__ u16   g_SPhi[CH * UDIM * UDIM], g_SPlo[CH * UDIM * UDIM];  // S^1..S^16
__device__ u16   g_S32hi[UDIM * UDIM], g_S32lo[UDIM * UDIM];          // S^32
__device__ u16   g_RPhi[6 * UDIM * UDIM], g_RPlo[6 * UDIM * UDIM];    // R^1,2,4,8,16,32
__device__ float g_W4F[UDIM * UDIM];        // S^64 fp32 (for serial chain)
__device__ float g_sP1[64 * BATCH * UDIM];  // s' level-1 combines
__device__ float g_sP2[32 * BATCH * UDIM];  // s'' level-2 combines
__device__ float g_gbuf[NCH * BATCH * UDIM];

#define MAX_BAR 2048
__device__ volatile unsigned g_bar[MAX_BAR];

__global__ void __launch_bounds__(256) bar_reset_kernel() {
    int i = blockIdx.x * blockDim.x + threadIdx.x;
    if (i < MAX_BAR) *(unsigned*)&g_bar[i] = 0u;
}
__global__ void __launch_bounds__(256) copy_h0_kernel(const float* __restrict__ h0,
                                                      float* __restrict__ g) {
    int i = blockIdx.x * blockDim.x + threadIdx.x;
    if (i < BATCH * UDIM) g[i] = h0[i];
}

// ---------------- helpers ----------------
__device__ __forceinline__ u32 smem_u32(const void* p) {
    u32 a;
    asm("{ .reg .u64 t; cvta.to.shared.u64 t, %1; cvt.u32.u64 %0, t; }"
        : "=r"(a) : "l"(p));
    return a;
}
#define SWZ(o) ((o) ^ (((o) >> 3) & 0x70))

__device__ __forceinline__ void bsplit(float v, u16& h, u16& l) {
    __nv_bfloat16 bh = __float2bfloat16_rn(v);
    float r = v - __bfloat162float(bh);
    __nv_bfloat16 bl = __float2bfloat16_rn(r);
    h = __bfloat16_as_ushort(bh);
    l = __bfloat16_as_ushort(bl);
}

__device__ __forceinline__ void ldsm4(u32 addr, u32& r0, u32& r1, u32& r2, u32& r3) {
    asm volatile("ldmatrix.sync.aligned.m8n8.x4.shared.b16 {%0,%1,%2,%3}, [%4];"
                 : "=r"(r0), "=r"(r1), "=r"(r2), "=r"(r3) : "r"(addr));
}
__device__ __forceinline__ void mma16816(float* d, const u32* a, const u32* b) {
    asm volatile(
        "mma.sync.aligned.m16n8k16.row.col.f32.bf16.bf16.f32 "
        "{%0,%1,%2,%3}, {%4,%5,%6,%7}, {%8,%9}, {%0,%1,%2,%3};"
        : "+f"(d[0]), "+f"(d[1]), "+f"(d[2]), "+f"(d[3])
        : "r"(a[0]), "r"(a[1]), "r"(a[2]), "r"(a[3]), "r"(b[0]), "r"(b[1]));
}

// ------------- split_gather: fp32 strided rows -> bf16 hi/lo natural -------
__global__ void __launch_bounds__(256) split_gather_kernel(
    const float* __restrict__ src, ll sB, ll sC,
    u16* __restrict__ hi, u16* __restrict__ lo)
{
    int m = blockIdx.x;
    int k = threadIdx.x * 4;
    ll off = (ll)(m & 31) * sB + (ll)(m >> 5) * sC + k;
    float4 v = *(const float4*)(src + off);
    u16 h0, h1, h2, h3, l0, l1, l2, l3;
    bsplit(v.x, h0, l0); bsplit(v.y, h1, l1);
    bsplit(v.z, h2, l2); bsplit(v.w, h3, l3);
    ll doff = (ll)m * 1024 + k;
    *(ushort4*)(hi + doff) = make_ushort4(h0, h1, h2, h3);
    *(ushort4*)(lo + doff) = make_ushort4(l0, l1, l2, l3);
}

// ------------- transpose_split: fp32 W[k][n] -> bf16 hi/lo of W^T [n][k] ----
__global__ void __launch_bounds__(256) transpose_split_kernel(
    const float* __restrict__ src, u16* __restrict__ thi, u16* __restrict__ tlo)
{
    __shared__ float tile[32][33];
    int bx = blockIdx.x * 32;   // n
    int by = blockIdx.y * 32;   // k
    int tx = threadIdx.x & 31;
    int ty = threadIdx.x >> 5;
#pragma unroll
    for (int i = 0; i < 32; i += 8)
        tile[ty + i][tx] = src[(ll)(by + ty + i) * 1024 + bx + tx];
    __syncthreads();
#pragma unroll
    for (int i = 0; i < 32; i += 8) {
        u16 h, l;
        bsplit(tile[tx][ty + i], h, l);
        ll off = (ll)(bx + ty + i) * 1024 + (by + tx);
        thi[off] = h;
        tlo[off] = l;
    }
}

// ---------------------------------------------------------------------------
// tgemm: C[m][n] = sum_{k<1024} Af[m][k]*Bf[n][k] via bf16 split, K'=3072:
//   region0 Ahi*Bhi, region1 Alo*Bhi, region2 Ahi*Blo (per 64-wide K chunk).
// mma.sync m16n8k16 bf16, CTA 128x128, BK=64 (SW128 rows), 3-stage cp.async.
// ONE barrier per chunk: the top-of-loop sync (after wait_group) both
// publishes cp.async data and guards stage reuse (write of stage (c-1)%3 in
// iter c happens after all readers of iter c-1 passed this barrier).
// ---------------------------------------------------------------------------
#define TG_STAGE 32768
#define TG_SMEM (3 * TG_STAGE)
#define TG_NCHK (KTOT / 64)

__global__ void __launch_bounds__(256, 2) tgemm_kernel(
    const u16* __restrict__ Ahi, const u16* __restrict__ Alo,
    const u16* __restrict__ Bhi, const u16* __restrict__ Blo,
    const float* __restrict__ Add, int adShift, ll adSB, ll adSC,
    float* __restrict__ OutF, ll ofSB, ll ofSC,
    u16* __restrict__ OBhi, u16* __restrict__ OBlo)
{
    extern __shared__ char smraw[];
    const u32 smbase = smem_u32(smraw);

    const int tid  = threadIdx.x;
    const int wid  = tid >> 5;
    const int lane = tid & 31;
    const ll mBase = (ll)blockIdx.y * 128;
    const ll nBase = (ll)blockIdx.x * 128;

    const int wm = (wid >> 1) * 32;
    const int wn = (wid & 1) * 64;

    float acc[2][8][4];
#pragma unroll
    for (int i = 0; i < 2; i++)
#pragma unroll
        for (int j = 0; j < 8; j++)
#pragma unroll
            for (int q = 0; q < 4; q++) acc[i][j][q] = 0.0f;

    auto load_chunk = [&](int c, int s) {
        const int reg = c >> 4;
        const u16* aptr = (reg == 1) ? Alo : Ahi;
        const u16* bptr = (reg == 2) ? Blo : Bhi;
        const ll kbase = (ll)(c & 15) * 64;
        u32 sa = smbase + (u32)s * TG_STAGE;
        u32 sb = sa + 16384;
#pragma unroll
        for (int i = 0; i < 4; i++) {
            int idx = i * 256 + tid;
            int row = idx >> 3;
            int cc  = (idx & 7) * 16;
            ll  kel = kbase + (idx & 7) * 8;
            asm volatile("cp.async.cg.shared.global [%0], [%1], 16;"
                :: "r"(sa + SWZ((u32)(row * 128 + cc))),
                   "l"((ull)(uintptr_t)(aptr + (mBase + row) * 1024 + kel)));
            asm volatile("cp.async.cg.shared.global [%0], [%1], 16;"
                :: "r"(sb + SWZ((u32)(row * 128 + cc))),
                   "l"((ull)(uintptr_t)(bptr + (nBase + row) * 1024 + kel)));
        }
        asm volatile("cp.async.commit_group;" ::: "memory");
    };

    load_chunk(0, 0);
    load_chunk(1, 1);

    const int aRow = (lane & 15);
    const int aKb  = (lane >> 4) * 16;
    const int bRow = (lane & 7) + ((lane >> 4) << 3);
    const int bKb  = ((lane >> 3) & 1) * 16;

#pragma unroll 1
    for (int c = 0; c < TG_NCHK; c++) {
        if (c + 2 < TG_NCHK) {
            asm volatile("cp.async.wait_group 1;" ::: "memory");
        } else {
            asm volatile("cp.async.wait_group 0;" ::: "memory");
        }
        __syncthreads();
        if (c + 2 < TG_NCHK) load_chunk(c + 2, (c + 2) % 3);

        u32 sa = smbase + (u32)(c % 3) * TG_STAGE;
        u32 sb = sa + 16384;

#pragma unroll
        for (int k16 = 0; k16 < 4; k16++) {
            const int kb = k16 * 32;
            u32 areg[2][4];
#pragma unroll
            for (int i = 0; i < 2; i++) {
                u32 ad = sa + SWZ((u32)((wm + i * 16 + aRow) * 128 + kb + aKb));
                ldsm4(ad, areg[i][0], areg[i][1], areg[i][2], areg[i][3]);
            }
            u32 breg[4][4];
#pragma unroll
            for (int j16 = 0; j16 < 4; j16++) {
                u32 bd = sb + SWZ((u32)((wn + j16 * 16 + bRow) * 128 + kb + bKb));
                ldsm4(bd, breg[j16][0], breg[j16][1], breg[j16][2], breg[j16][3]);
            }
#pragma unroll
            for (int i = 0; i < 2; i++)
#pragma unroll
                for (int j = 0; j < 8; j++)
                    mma16816(acc[i][j], areg[i], &breg[j >> 1][(j & 1) * 2]);
        }
        // no trailing barrier: next iteration's top barrier guards reuse
    }

    const int g  = lane >> 2;
    const int tg = (lane & 3) * 2;

#pragma unroll
    for (int i = 0; i < 2; i++) {
#pragma unroll
        for (int half = 0; half < 2; half++) {
            ll m = mBase + wm + i * 16 + g + half * 8;
            const float* addp = Add ?
                Add + (m & ((1 << adShift) - 1)) * adSB + (m >> adShift) * adSC + nBase
                : (const float*)0;
            float* ofp = OutF ?
                OutF + (m & 31) * ofSB + (m >> 5) * ofSC + nBase : (float*)0;
            u16* obh = OBhi ? OBhi + m * 1024 + nBase : (u16*)0;
            u16* obl = OBlo ? OBlo + m * 1024 + nBase : (u16*)0;
#pragma unroll
            for (int j = 0; j < 8; j++) {
                int n = wn + j * 8 + tg;
                float v0 = acc[i][j][half * 2 + 0];
                float v1 = acc[i][j][half * 2 + 1];
                if (addp) {
                    float2 a = *(const float2*)(addp + n);
                    v0 += a.x; v1 += a.y;
                }
                if (ofp)
                    *(float2*)(ofp + n) = make_float2(v0, v1);
                if (obh) {
                    u16 h0, h1, l0, l1;
                    bsplit(v0, h0, l0);
                    bsplit(v1, h1, l1);
                    *(ushort2*)(obh + n) = make_ushort2(h0, h1);
                    *(ushort2*)(obl + n) = make_ushort2(l0, l1);
                }
            }
        }
    }
}

// ---------------------------------------------------------------------------
// phase2: serial carry chain G[e+1] = G[e] @ W + u[e]  (fp32, persistent)
// ---------------------------------------------------------------------------
__device__ __forceinline__ void ffma2(ull& d, ull a, ull b) {
    asm volatile("fma.rn.f32x2 %0, %1, %2, %0;" : "+l"(d) : "l"(a), "l"(b));
}
__device__ __forceinline__ float2 u2f2(ull v) {
    float2 f;
    f.x = __uint_as_float((unsigned)(v & 0xffffffffull));
    f.y = __uint_as_float((unsigned)(v >> 32));
    return f;
}
__device__ __forceinline__ float4 ldcg4(const float* p) {
    float4 v;
    asm volatile("ld.global.cg.v4.f32 {%0,%1,%2,%3}, [%4];"
                 : "=f"(v.x), "=f"(v.y), "=f"(v.z), "=f"(v.w) : "l"(p));
    return v;
}
#define P2_RPAD 1028
#define P2_HPAD 1032
#define P2_HS_OFF (32 * P2_RPAD)
#define P2_SMEM_FLOATS (32 * P2_RPAD + 8 * P2_HPAD)
#define P2_CTAS 128

__global__ void __launch_bounds__(256) phase2_kernel(
    const float* __restrict__ ST,
    const float* __restrict__ u, ll uSB, ll uSC,
    float* __restrict__ g, ll gStep, int steps)
{
    extern __shared__ float sm[];
    const int tid = threadIdx.x;
    const int col0 = (blockIdx.x & 31) * 32;
    const int b0   = (blockIdx.x >> 5) * 8;

    for (int idx = tid; idx < 32 * 1024; idx += 256) {
        int j = idx >> 10, k = idx & 1023;
        sm[j * P2_RPAD + k] = ST[(size_t)(col0 + j) * 1024 + k];
    }
    __syncthreads();

    const int j = tid & 31;
    const int b = tid >> 5;
    const float* Rrow = &sm[j * P2_RPAD];
    const float* hrow = &sm[P2_HS_OFF + b * P2_HPAD];
    const unsigned P = gridDim.x;

    for (int c = 0; c < steps; c++) {
        const float* gsrc = g + (ll)c * gStep;
        for (int i = tid; i < 2048; i += 256) {
            int bb = i >> 8, kk = (i & 255) * 4;
            float4 v = ldcg4(gsrc + (size_t)(b0 + bb) * UDIM + kk);
            *(float4*)&sm[P2_HS_OFF + bb * P2_HPAD + kk] = v;
        }
        __syncthreads();

        ull a0 = 0, a1 = 0, a2 = 0, a3 = 0;
#pragma unroll 4
        for (int k = 0; k < 1024; k += 8) {
            ulonglong2 h01 = *(const ulonglong2*)(hrow + k);
            ulonglong2 h23 = *(const ulonglong2*)(hrow + k + 4);
            ulonglong2 r01 = *(const ulonglong2*)(Rrow + k);
            ulonglong2 r23 = *(const ulonglong2*)(Rrow + k + 4);
            ffma2(a0, h01.x, r01.x); ffma2(a1, h01.y, r01.y);
            ffma2(a2, h23.x, r23.x); ffma2(a3, h23.y, r23.y);
        }
        float2 f0 = u2f2(a0), f1 = u2f2(a1), f2 = u2f2(a2), f3 = u2f2(a3);
        float sum = ((f0.x + f0.y) + (f1.x + f1.y)) +
                    ((f2.x + f2.y) + (f3.x + f3.y));

        float uv = __ldg(u + (ll)(b0 + b) * uSB + (ll)c * uSC + col0 + j);
        g[(ll)(c + 1) * gStep + (size_t)(b0 + b) * UDIM + col0 + j] = sum + uv;

        __threadfence();
        __syncthreads();
        if (tid == 0) {
            unsigned arrived = atomicAdd((unsigned*)&g_bar[c], 1u) + 1u;
            if (arrived < P) {
                while (g_bar[c] < P) { }
            }
            __threadfence();
        }
        __syncthreads();
    }
}

// ---------------------------------------------------------------------------
extern "C" void kernel_launch(void* const* d_in, const int* in_sizes, int n_in,
                              void* d_out, int out_size)
{
    const float* x    = (const float*)d_in[0];
    const float* h0   = (const float*)d_in[1];
    const float* cst  = (const float*)d_in[2];
    const float* kern = (const float*)d_in[3];
    const float* rker = (const float*)d_in[4];
    float* out = (float*)d_out;

    const ll TU = (ll)TDIM * UDIM;
    const ll CU = (ll)CH * UDIM;
    const ll SL = (ll)UDIM * UDIM;
    const ll GB = (ll)BATCH * UDIM;

    u16 *Xhi, *Xlo, *UAhi, *UAlo, *UBhi, *UBlo, *KThi, *KTlo;
    u16 *SPhi, *SPlo, *RPhi, *RPlo, *S32hi, *S32lo;
    float *W4F, *sP1, *sP2, *gbuf;
    cudaGetSymbolAddress((void**)&Xhi, g_Xhi);   cudaGetSymbolAddress((void**)&Xlo, g_Xlo);
    cudaGetSymbolAddress((void**)&UAhi, g_UAhi); cudaGetSymbolAddress((void**)&UAlo, g_UAlo);
    cudaGetSymbolAddress((void**)&UBhi, g_UBhi); cudaGetSymbolAddress((void**)&UBlo, g_UBlo);
    cudaGetSymbolAddress((void**)&KThi, g_KThi); cudaGetSymbolAddress((void**)&KTlo, g_KTlo);
    cudaGetSymbolAddress((void**)&SPhi, g_SPhi); cudaGetSymbolAddress((void**)&SPlo, g_SPlo);
    cudaGetSymbolAddress((void**)&RPhi, g_RPhi); cudaGetSymbolAddress((void**)&RPlo, g_RPlo);
    cudaGetSymbolAddress((void**)&S32hi, g_S32hi); cudaGetSymbolAddress((void**)&S32lo, g_S32lo);
    cudaGetSymbolAddress((void**)&W4F, g_W4F);
    cudaGetSymbolAddress((void**)&sP1, g_sP1);
    cudaGetSymbolAddress((void**)&sP2, g_sP2);
    cudaGetSymbolAddress((void**)&gbuf, g_gbuf);

    cudaFuncSetAttribute(tgemm_kernel,
        cudaFuncAttributeMaxDynamicSharedMemorySize, TG_SMEM);
    cudaFuncSetAttribute(phase2_kernel,
        cudaFuncAttributeMaxDynamicSharedMemorySize, P2_SMEM_FLOATS * 4);

    // ---- side stream + events (created once; capture-safe fork/join) ----
    static cudaStream_t s2 = (cudaStream_t)0;
    static cudaEvent_t evFork = 0, evS1 = 0, evJoin = 0;
    static bool tried = false;
    if (!tried) {
        tried = true;
        if (cudaStreamCreateWithFlags(&s2, cudaStreamNonBlocking) != cudaSuccess)
            s2 = (cudaStream_t)0;
        cudaEventCreateWithFlags(&evFork, cudaEventDisableTiming);
        cudaEventCreateWithFlags(&evS1,   cudaEventDisableTiming);
        cudaEventCreateWithFlags(&evJoin, cudaEventDisableTiming);
    }

    // fork side chain from the main (capture) stream
    cudaEventRecord(evFork, 0);
    cudaStreamWaitEvent(s2, evFork, 0);

    // ======== side chain (stream s2): R-derived prep + power chain ========
    bar_reset_kernel<<<(MAX_BAR + 255) / 256, 256, 0, s2>>>();
    transpose_split_kernel<<<dim3(32, 32), 256, 0, s2>>>(rker, SPhi, SPlo);   // S^1
    cudaEventRecord(evS1, s2);   // phase 1 only needs S^1
    split_gather_kernel<<<UDIM, 256, 0, s2>>>(rker, 1024, 32768, RPhi, RPlo); // R^1
    copy_h0_kernel<<<(BATCH * UDIM + 255) / 256, 256, 0, s2>>>(h0, gbuf);
    {
        dim3 g1(8, 8), g2(8, 16), g4(8, 32), g8(8, 64);
        tgemm_kernel<<<g1, 256, TG_SMEM, s2>>>(SPhi, SPlo, RPhi, RPlo,          // S^2
            nullptr, 5, 0, 0, nullptr, 0, 0, SPhi + SL, SPlo + SL);
        tgemm_kernel<<<g1, 256, TG_SMEM, s2>>>(RPhi, RPlo, SPhi, SPlo,          // R^2
            nullptr, 5, 0, 0, nullptr, 0, 0, RPhi + SL, RPlo + SL);
        tgemm_kernel<<<g2, 256, TG_SMEM, s2>>>(SPhi, SPlo, RPhi + SL, RPlo + SL,// S^3,4
            nullptr, 5, 0, 0, nullptr, 0, 0, SPhi + 2 * SL, SPlo + 2 * SL);
        tgemm_kernel<<<g1, 256, TG_SMEM, s2>>>(RPhi + SL, RPlo + SL,            // R^4
            SPhi + SL, SPlo + SL,
            nullptr, 5, 0, 0, nullptr, 0, 0, RPhi + 2 * SL, RPlo + 2 * SL);
        tgemm_kernel<<<g4, 256, TG_SMEM, s2>>>(SPhi, SPlo,                      // S^5..8
            RPhi + 2 * SL, RPlo + 2 * SL,
            nullptr, 5, 0, 0, nullptr, 0, 0, SPhi + 4 * SL, SPlo + 4 * SL);
        tgemm_kernel<<<g1, 256, TG_SMEM, s2>>>(RPhi + 2 * SL, RPlo + 2 * SL,    // R^8
            SPhi + 3 * SL, SPlo + 3 * SL,
            nullptr, 5, 0, 0, nullptr, 0, 0, RPhi + 3 * SL, RPlo + 3 * SL);
        tgemm_kernel<<<g8, 256, TG_SMEM, s2>>>(SPhi, SPlo,                      // S^9..16
            RPhi + 3 * SL, RPlo + 3 * SL,
            nullptr, 5, 0, 0, nullptr, 0, 0, SPhi + 8 * SL, SPlo + 8 * SL);
        tgemm_kernel<<<g1, 256, TG_SMEM, s2>>>(RPhi + 3 * SL, RPlo + 3 * SL,    // R^16
            SPhi + 7 * SL, SPlo + 7 * SL,
            nullptr, 5, 0, 0, nullptr, 0, 0, RPhi + 4 * SL, RPlo + 4 * SL);
        tgemm_kernel<<<g1, 256, TG_SMEM, s2>>>(RPhi + 4 * SL, RPlo + 4 * SL,    // R^32
            SPhi + 15 * SL, SPlo + 15 * SL,
            nullptr, 5, 0, 0, nullptr, 0, 0, RPhi + 5 * SL, RPlo + 5 * SL);
        tgemm_kernel<<<g1, 256, TG_SMEM, s2>>>(SPhi + 15 * SL, SPlo + 15 * SL,  // S^32
            RPhi + 4 * SL, RPlo + 4 * SL,
            nullptr, 5, 0, 0, nullptr, 0, 0, S32hi, S32lo);
        tgemm_kernel<<<g1, 256, TG_SMEM, s2>>>(S32hi, S32lo,                    // S^64 fp32
            RPhi + 5 * SL, RPlo + 5 * SL,
            nullptr, 5, 0, 0, W4F, 1024, 32768, nullptr, nullptr);
    }
    cudaEventRecord(evJoin, s2);

    // ======== main chain (default stream) ========
    split_gather_kernel<<<BATCH * TDIM, 256>>>(x, 1024, 32768, Xhi, Xlo);
    transpose_split_kernel<<<dim3(32, 32), 256>>>(kern, KThi, KTlo);

    // phase 0: xw = x @ kernel + const -> out (rows m = b*T + t)
    {
        dim3 g0(8, 512);
        tgemm_kernel<<<g0, 256, TG_SMEM>>>(Xhi, Xlo, KThi, KTlo,
            cst, 11, 0, 1024,
            out, 1024, 32768,
            nullptr, nullptr);
    }

    // gather xw rows at t = c*CH (chunk heads), split -> UA  (m = c*32+b)
    split_gather_kernel<<<NCH * BATCH, 256>>>(out, TU, CU, UAhi, UAlo);

    // phase 1 needs S^1 from side chain
    cudaStreamWaitEvent(0, evS1, 0);

    // phase 1: Horner u_j = u_{j-1} @ R + xw_{c*CH+j}, j = 1..CH-1.
    {
        dim3 gp(8, 32);   // M = 4096
        for (int jj = 1; jj < CH; jj++) {
            const u16* ah = (jj & 1) ? UAhi : UBhi;
            const u16* al = (jj & 1) ? UAlo : UBlo;
            u16* oh = (jj & 1) ? UBhi : UAhi;
            u16* ol = (jj & 1) ? UBlo : UAlo;
            bool last = (jj == CH - 1);
            tgemm_kernel<<<gp, 256, TG_SMEM>>>(ah, al, SPhi, SPlo,
                out + (size_t)jj * UDIM, 5, TU, CU,
                out + (size_t)jj * UDIM, TU, CU,
                last ? nullptr : oh, last ? nullptr : ol);
        }
    }

    // join: combines/phase2/phase3 need all powers + bar_reset + h0 copy
    cudaStreamWaitEvent(0, evJoin, 0);

    // ---- phase 2 (radix-4 reduced): chain g_{c+1} = g_c W + s_c, W = R^16 ----
    const float* sBase = out + (size_t)(CH - 1) * UDIM;  // s_c at t = c*16+15

    // combine1: s'_d = s_{2d} W + s_{2d+1}  (d = 0..63, M = 2048)
    split_gather_kernel<<<2048, 256>>>(sBase, TU, 2 * CU, UBhi, UBlo);
    {
        dim3 gp(8, 16);
        tgemm_kernel<<<gp, 256, TG_SMEM>>>(UBhi, UBlo,
            SPhi + 15 * SL, SPlo + 15 * SL,
            sBase + CU, 5, TU, 2 * CU,
            sP1, 1024, 32768,
            nullptr, nullptr);
    }
    // combine2: s''_e = s'_{2e} W^2 + s'_{2e+1}  (e = 0..31, M = 1024)
    split_gather_kernel<<<1024, 256>>>(sP1, 1024, 2 * 32768, UBhi, UBlo);
    {
        dim3 gp(8, 8);
        tgemm_kernel<<<gp, 256, TG_SMEM>>>(UBhi, UBlo, S32hi, S32lo,
            sP1 + 32768, 5, 1024, 2 * 32768,
            sP2, 1024, 32768,
            nullptr, nullptr);
    }
    // serial chain (31 steps): g_{4(e+1)} = g_{4e} W^4 + s''_e
    phase2_kernel<<<P2_CTAS, 256, P2_SMEM_FLOATS * 4>>>(
        W4F, sP2, 1024, 32768, gbuf, 4 * GB, 32 - 1);
    // backfill2: g_{4e+2} = g_{4e} W^2 + s'_{2e}  (e = 0..31, M = 1024)
    split_gather_kernel<<<1024, 256>>>(gbuf, 1024, 4 * 32768, UBhi, UBlo);
    {
        dim3 gp(8, 8);
        tgemm_kernel<<<gp, 256, TG_SMEM>>>(UBhi, UBlo, S32hi, S32lo,
            sP1, 5, 1024, 2 * 32768,
            gbuf + 2 * GB, 1024, 4 * 32768,
            nullptr, nullptr);
    }
    // backfill1: g_{2d+1} = g_{2d} W + s_{2d}  (d = 0..63, M = 2048)
    split_gather_kernel<<<2048, 256>>>(gbuf, 1024, 2 * 32768, UBhi, UBlo);
    {
        dim3 gp(8, 16);
        tgemm_kernel<<<gp, 256, TG_SMEM>>>(UBhi, UBlo,
            SPhi + 15 * SL, SPlo + 15 * SL,
            sBase, 5, TU, 2 * CU,
            gbuf + GB, 1024, 2 * 32768,
            nullptr, nullptr);
    }

    // split all carries -> UA  (m = c*32+b)
    split_gather_kernel<<<NCH * BATCH, 256>>>(gbuf, 1024, 32768, UAhi, UAlo);

    // phase 3 (single GEMM): out_{c*CH+j} += g_c @ R^{j+1} for all j at once.
    {
        dim3 gp(CH * 1024 / 128, 32);   // (128, 32) = 4096 CTAs
        tgemm_kernel<<<gp, 256, TG_SMEM>>>(UAhi, UAlo, SPhi, SPlo,
            out, 5, TU, CU,
            out, TU, CU,
            nullptr, nullptr);
    }
}

// round 10
// speedup vs baseline: 1.4896x; 1.0200x over previous
#include <cuda_runtime.h>
#include <cuda_bf16.h>
#include <cstdint>

typedef unsigned long long ull;
typedef long long ll;
typedef unsigned short u16;
typedef unsigned int u32;

#define UDIM 1024
#define BATCH 32
#define TDIM 2048
#define CH 16
#define NCH (TDIM / CH)          // 128
#define KTOT 3072
#define SLE (1024 * 1024)        // one UxU matrix, elements

// ---------------- scratch (device globals; no runtime alloc) ----------------
__device__ u16   g_Xhi[(size_t)BATCH * TDIM * UDIM];
__device__ u16   g_Xlo[(size_t)BATCH * TDIM * UDIM];
__device__ u16   g_UAhi[NCH * BATCH * UDIM], g_UAlo[NCH * BATCH * UDIM];
__device__ u16   g_UBhi[NCH * BATCH * UDIM], g_UBlo[NCH * BATCH * UDIM];
__device__ u16   g_KThi[SLE], g_KTlo[SLE];
__device__ u16   g_SPhi[CH * SLE], g_SPlo[CH * SLE];    // S^1..S^16
__device__ u16   g_S32hi[SLE], g_S32lo[SLE];            // S^32
__device__ u16   g_S64hi[SLE], g_S64lo[SLE];            // S^64
__device__ u16   g_RPhi[7 * SLE], g_RPlo[7 * SLE];      // R^1,2,4,8,16,32,64
__device__ u16   g_C1hi[64 * BATCH * UDIM], g_C1lo[64 * BATCH * UDIM];
__device__ u16   g_C2hi[32 * BATCH * UDIM], g_C2lo[32 * BATCH * UDIM];
__device__ u16   g_GChi[NCH * BATCH * UDIM], g_GClo[NCH * BATCH * UDIM];
__device__ float g_W8F[SLE];                // S^128 fp32 (serial chain weight)
__device__ float g_sP1[64 * BATCH * UDIM];
__device__ float g_sP2[32 * BATCH * UDIM];
__device__ float g_sP3[16 * BATCH * UDIM];
__device__ float g_gbuf[NCH * BATCH * UDIM];

#define MAX_BAR 2048
__device__ volatile unsigned g_bar[MAX_BAR];

__global__ void __launch_bounds__(256) bar_reset_kernel() {
    int i = blockIdx.x * blockDim.x + threadIdx.x;
    if (i < MAX_BAR) *(unsigned*)&g_bar[i] = 0u;
}

// ---------------- helpers ----------------
__device__ __forceinline__ u32 smem_u32(const void* p) {
    u32 a;
    asm("{ .reg .u64 t; cvta.to.shared.u64 t, %1; cvt.u32.u64 %0, t; }"
        : "=r"(a) : "l"(p));
    return a;
}
#define SWZ(o) ((o) ^ (((o) >> 3) & 0x70))

__device__ __forceinline__ void bsplit(float v, u16& h, u16& l) {
    __nv_bfloat16 bh = __float2bfloat16_rn(v);
    float r = v - __bfloat162float(bh);
    __nv_bfloat16 bl = __float2bfloat16_rn(r);
    h = __bfloat16_as_ushort(bh);
    l = __bfloat16_as_ushort(bl);
}

__global__ void __launch_bounds__(256) copy_h0_kernel(
    const float* __restrict__ h0, float* __restrict__ g,
    u16* __restrict__ GCh, u16* __restrict__ GCl)
{
    int i = blockIdx.x * blockDim.x + threadIdx.x;
    if (i < BATCH * UDIM) {
        float v = h0[i];
        g[i] = v;
        u16 h, l;
        bsplit(v, h, l);
        GCh[i] = h; GCl[i] = l;
    }
}

__device__ __forceinline__ void ldsm4(u32 addr, u32& r0, u32& r1, u32& r2, u32& r3) {
    asm volatile("ldmatrix.sync.aligned.m8n8.x4.shared.b16 {%0,%1,%2,%3}, [%4];"
                 : "=r"(r0), "=r"(r1), "=r"(r2), "=r"(r3) : "r"(addr));
}
__device__ __forceinline__ void mma16816(float* d, const u32* a, const u32* b) {
    asm volatile(
        "mma.sync.aligned.m16n8k16.row.col.f32.bf16.bf16.f32 "
        "{%0,%1,%2,%3}, {%4,%5,%6,%7}, {%8,%9}, {%0,%1,%2,%3};"
        : "+f"(d[0]), "+f"(d[1]), "+f"(d[2]), "+f"(d[3])
        : "r"(a[0]), "r"(a[1]), "r"(a[2]), "r"(a[3]), "r"(b[0]), "r"(b[1]));
}

// ------------- split_gather: fp32 strided rows -> bf16 hi/lo natural -------
__global__ void __launch_bounds__(256) split_gather_kernel(
    const float* __restrict__ src, ll sB, ll sC,
    u16* __restrict__ hi, u16* __restrict__ lo)
{
    int m = blockIdx.x;
    int k = threadIdx.x * 4;
    ll off = (ll)(m & 31) * sB + (ll)(m >> 5) * sC + k;
    float4 v = *(const float4*)(src + off);
    u16 h0, h1, h2, h3, l0, l1, l2, l3;
    bsplit(v.x, h0, l0); bsplit(v.y, h1, l1);
    bsplit(v.z, h2, l2); bsplit(v.w, h3, l3);
    ll doff = (ll)m * 1024 + k;
    *(ushort4*)(hi + doff) = make_ushort4(h0, h1, h2, h3);
    *(ushort4*)(lo + doff) = make_ushort4(l0, l1, l2, l3);
}

// ------------- transpose_split: fp32 W[k][n] -> bf16 hi/lo of W^T [n][k] ----
__global__ void __launch_bounds__(256) transpose_split_kernel(
    const float* __restrict__ src, u16* __restrict__ thi, u16* __restrict__ tlo)
{
    __shared__ float tile[32][33];
    int bx = blockIdx.x * 32;
    int by = blockIdx.y * 32;
    int tx = threadIdx.x & 31;
    int ty = threadIdx.x >> 5;
#pragma unroll
    for (int i = 0; i < 32; i += 8)
        tile[ty + i][tx] = src[(ll)(by + ty + i) * 1024 + bx + tx];
    __syncthreads();
#pragma unroll
    for (int i = 0; i < 32; i += 8) {
        u16 h, l;
        bsplit(tile[tx][ty + i], h, l);
        ll off = (ll)(bx + ty + i) * 1024 + (by + tx);
        thi[off] = h;
        tlo[off] = l;
    }
}

// ---------------------------------------------------------------------------
// tgemm: C[m][n] = sum_{k<1024} Af[m][k]*Bf[n][k] via bf16 split, K'=3072.
// ALL row mappings are (m&31)*SB + (m>>5)*SC (+ base pointer):
//   A (bf16 hi/lo), Add (fp32, nullable), OutF (fp32, nullable),
//   OB (bf16 hi/lo re-split, nullable). B is natural [n][k].
// mma.sync m16n8k16 bf16, CTA 128x128, BK=64, 3-stage cp.async, 1 barrier/chunk.
// ---------------------------------------------------------------------------
#define TG_STAGE 32768
#define TG_SMEM (3 * TG_STAGE)
#define TG_NCHK (KTOT / 64)

__global__ void __launch_bounds__(256, 2) tgemm_kernel(
    const u16* __restrict__ Ahi, const u16* __restrict__ Alo, ll aSB, ll aSC,
    const u16* __restrict__ Bhi, const u16* __restrict__ Blo,
    const float* __restrict__ Add, ll adSB, ll adSC,
    float* __restrict__ OutF, ll ofSB, ll ofSC,
    u16* __restrict__ OBhi, u16* __restrict__ OBlo, ll obSB, ll obSC)
{
    extern __shared__ char smraw[];
    const u32 smbase = smem_u32(smraw);

    const int tid  = threadIdx.x;
    const int wid  = tid >> 5;
    const int lane = tid & 31;
    const ll mBase = (ll)blockIdx.y * 128;
    const ll nBase = (ll)blockIdx.x * 128;

    const int wm = (wid >> 1) * 32;
    const int wn = (wid & 1) * 64;

    float acc[2][8][4];
#pragma unroll
    for (int i = 0; i < 2; i++)
#pragma unroll
        for (int j = 0; j < 8; j++)
#pragma unroll
            for (int q = 0; q < 4; q++) acc[i][j][q] = 0.0f;

    auto load_chunk = [&](int c, int s) {
        const int reg = c >> 4;
        const u16* aptr = (reg == 1) ? Alo : Ahi;
        const u16* bptr = (reg == 2) ? Blo : Bhi;
        const ll kbase = (ll)(c & 15) * 64;
        u32 sa = smbase + (u32)s * TG_STAGE;
        u32 sb = sa + 16384;
#pragma unroll
        for (int i = 0; i < 4; i++) {
            int idx = i * 256 + tid;
            int row = idx >> 3;
            int cc  = (idx & 7) * 16;
            ll  kel = kbase + (idx & 7) * 8;
            ll  rm  = mBase + row;
            asm volatile("cp.async.cg.shared.global [%0], [%1], 16;"
                :: "r"(sa + SWZ((u32)(row * 128 + cc))),
                   "l"((ull)(uintptr_t)(aptr + (rm & 31) * aSB + (rm >> 5) * aSC + kel)));
            asm volatile("cp.async.cg.shared.global [%0], [%1], 16;"
                :: "r"(sb + SWZ((u32)(row * 128 + cc))),
                   "l"((ull)(uintptr_t)(bptr + (nBase + row) * 1024 + kel)));
        }
        asm volatile("cp.async.commit_group;" ::: "memory");
    };

    load_chunk(0, 0);
    load_chunk(1, 1);

    const int aRow = (lane & 15);
    const int aKb  = (lane >> 4) * 16;
    const int bRow = (lane & 7) + ((lane >> 4) << 3);
    const int bKb  = ((lane >> 3) & 1) * 16;

#pragma unroll 1
    for (int c = 0; c < TG_NCHK; c++) {
        if (c + 2 < TG_NCHK) {
            asm volatile("cp.async.wait_group 1;" ::: "memory");
        } else {
            asm volatile("cp.async.wait_group 0;" ::: "memory");
        }
        __syncthreads();
        if (c + 2 < TG_NCHK) load_chunk(c + 2, (c + 2) % 3);

        u32 sa = smbase + (u32)(c % 3) * TG_STAGE;
        u32 sb = sa + 16384;

#pragma unroll
        for (int k16 = 0; k16 < 4; k16++) {
            const int kb = k16 * 32;
            u32 areg[2][4];
#pragma unroll
            for (int i = 0; i < 2; i++) {
                u32 ad = sa + SWZ((u32)((wm + i * 16 + aRow) * 128 + kb + aKb));
                ldsm4(ad, areg[i][0], areg[i][1], areg[i][2], areg[i][3]);
            }
            u32 breg[4][4];
#pragma unroll
            for (int j16 = 0; j16 < 4; j16++) {
                u32 bd = sb + SWZ((u32)((wn + j16 * 16 + bRow) * 128 + kb + bKb));
                ldsm4(bd, breg[j16][0], breg[j16][1], breg[j16][2], breg[j16][3]);
            }
#pragma unroll
            for (int i = 0; i < 2; i++)
#pragma unroll
                for (int j = 0; j < 8; j++)
                    mma16816(acc[i][j], areg[i], &breg[j >> 1][(j & 1) * 2]);
        }
    }

    const int g  = lane >> 2;
    const int tg = (lane & 3) * 2;

#pragma unroll
    for (int i = 0; i < 2; i++) {
#pragma unroll
        for (int half = 0; half < 2; half++) {
            ll m = mBase + wm + i * 16 + g + half * 8;
            ll roff = (m & 31);
            ll coff = (m >> 5);
            const float* addp = Add ?
                Add + roff * adSB + coff * adSC + nBase : (const float*)0;
            float* ofp = OutF ?
                OutF + roff * ofSB + coff * ofSC + nBase : (float*)0;
            u16* obh = OBhi ? OBhi + roff * obSB + coff * obSC + nBase : (u16*)0;
            u16* obl = OBlo ? OBlo + roff * obSB + coff * obSC + nBase : (u16*)0;
#pragma unroll
            for (int j = 0; j < 8; j++) {
                int n = wn + j * 8 + tg;
                float v0 = acc[i][j][half * 2 + 0];
                float v1 = acc[i][j][half * 2 + 1];
                if (addp) {
                    float2 a = *(const float2*)(addp + n);
                    v0 += a.x; v1 += a.y;
                }
                if (ofp)
                    *(float2*)(ofp + n) = make_float2(v0, v1);
                if (obh) {
                    u16 h0, h1, l0, l1;
                    bsplit(v0, h0, l0);
                    bsplit(v1, h1, l1);
                    *(ushort2*)(obh + n) = make_ushort2(h0, h1);
                    *(ushort2*)(obl + n) = make_ushort2(l0, l1);
                }
            }
        }
    }
}

// ---------------------------------------------------------------------------
// phase2: serial carry chain G[c+1] = G[c] @ W + u[c]; emits bf16 split of
// each produced state into GC at stride gcStep (natural carry-major).
// ---------------------------------------------------------------------------
__device__ __forceinline__ void ffma2(ull& d, ull a, ull b) {
    asm volatile("fma.rn.f32x2 %0, %1, %2, %0;" : "+l"(d) : "l"(a), "l"(b));
}
__device__ __forceinline__ float2 u2f2(ull v) {
    float2 f;
    f.x = __uint_as_float((unsigned)(v & 0xffffffffull));
    f.y = __uint_as_float((unsigned)(v >> 32));
    return f;
}
__device__ __forceinline__ float4 ldcg4(const float* p) {
    float4 v;
    asm volatile("ld.global.cg.v4.f32 {%0,%1,%2,%3}, [%4];"
                 : "=f"(v.x), "=f"(v.y), "=f"(v.z), "=f"(v.w) : "l"(p));
    return v;
}
#define P2_RPAD 1028
#define P2_HPAD 1032
#define P2_HS_OFF (32 * P2_RPAD)
#define P2_SMEM_FLOATS (32 * P2_RPAD + 8 * P2_HPAD)
#define P2_CTAS 128

__global__ void __launch_bounds__(256) phase2_kernel(
    const float* __restrict__ ST,
    const float* __restrict__ u, ll uSB, ll uSC,
    float* __restrict__ g, ll gStep,
    u16* __restrict__ GCh, u16* __restrict__ GCl, ll gcStep,
    int steps)
{
    extern __shared__ float sm[];
    const int tid = threadIdx.x;
    const int col0 = (blockIdx.x & 31) * 32;
    const int b0   = (blockIdx.x >> 5) * 8;

    for (int idx = tid; idx < 32 * 1024; idx += 256) {
        int j = idx >> 10, k = idx & 1023;
        sm[j * P2_RPAD + k] = ST[(size_t)(col0 + j) * 1024 + k];
    }
    __syncthreads();

    const int j = tid & 31;
    const int b = tid >> 5;
    const float* Rrow = &sm[j * P2_RPAD];
    const float* hrow = &sm[P2_HS_OFF + b * P2_HPAD];
    const unsigned P = gridDim.x;

    for (int c = 0; c < steps; c++) {
        const float* gsrc = g + (ll)c * gStep;
        for (int i = tid; i < 2048; i += 256) {
            int bb = i >> 8, kk = (i & 255) * 4;
            float4 v = ldcg4(gsrc + (size_t)(b0 + bb) * UDIM + kk);
            *(float4*)&sm[P2_HS_OFF + bb * P2_HPAD + kk] = v;
        }
        __syncthreads();

        ull a0 = 0, a1 = 0, a2 = 0, a3 = 0;
#pragma unroll 4
        for (int k = 0; k < 1024; k += 8) {
            ulonglong2 h01 = *(const ulonglong2*)(hrow + k);
            ulonglong2 h23 = *(const ulonglong2*)(hrow + k + 4);
            ulonglong2 r01 = *(const ulonglong2*)(Rrow + k);
            ulonglong2 r23 = *(const ulonglong2*)(Rrow + k + 4);
            ffma2(a0, h01.x, r01.x); ffma2(a1, h01.y, r01.y);
            ffma2(a2, h23.x, r23.x); ffma2(a3, h23.y, r23.y);
        }
        float2 f0 = u2f2(a0), f1 = u2f2(a1), f2 = u2f2(a2), f3 = u2f2(a3);
        float sum = ((f0.x + f0.y) + (f1.x + f1.y)) +
                    ((f2.x + f2.y) + (f3.x + f3.y));

        float uv = __ldg(u + (ll)(b0 + b) * uSB + (ll)c * uSC + col0 + j);
        float val = sum + uv;
        ll eoff = (ll)(b0 + b) * UDIM + col0 + j;
        g[(ll)(c + 1) * gStep + eoff] = val;
        {
            u16 hh, lw;
            bsplit(val, hh, lw);
            ll gco = (ll)(c + 1) * gcStep + eoff;
            GCh[gco] = hh; GCl[gco] = lw;
        }

        __threadfence();
        __syncthreads();
        if (tid == 0) {
            unsigned arrived = atomicAdd((unsigned*)&g_bar[c], 1u) + 1u;
            if (arrived < P) {
                while (g_bar[c] < P) { }
            }
            __threadfence();
        }
        __syncthreads();
    }
}

// ---------------------------------------------------------------------------
extern "C" void kernel_launch(void* const* d_in, const int* in_sizes, int n_in,
                              void* d_out, int out_size)
{
    const float* x    = (const float*)d_in[0];
    const float* h0   = (const float*)d_in[1];
    const float* cst  = (const float*)d_in[2];
    const float* kern = (const float*)d_in[3];
    const float* rker = (const float*)d_in[4];
    float* out = (float*)d_out;

    const ll TU = (ll)TDIM * UDIM;
    const ll CU = (ll)CH * UDIM;
    const ll SL = (ll)SLE;
    const ll GB = (ll)BATCH * UDIM;
    const ll NAT_B = 1024, NAT_C = 32768;   // natural (m&31, m>>5) strides

    u16 *Xhi, *Xlo, *UAhi, *UAlo, *UBhi, *UBlo, *KThi, *KTlo;
    u16 *SPhi, *SPlo, *RPhi, *RPlo, *S32hi, *S32lo, *S64hi, *S64lo;
    u16 *C1hi, *C1lo, *C2hi, *C2lo, *GChi, *GClo;
    float *W8F, *sP1, *sP2, *sP3, *gbuf;
    cudaGetSymbolAddress((void**)&Xhi, g_Xhi);   cudaGetSymbolAddress((void**)&Xlo, g_Xlo);
    cudaGetSymbolAddress((void**)&UAhi, g_UAhi); cudaGetSymbolAddress((void**)&UAlo, g_UAlo);
    cudaGetSymbolAddress((void**)&UBhi, g_UBhi); cudaGetSymbolAddress((void**)&UBlo, g_UBlo);
    cudaGetSymbolAddress((void**)&KThi, g_KThi); cudaGetSymbolAddress((void**)&KTlo, g_KTlo);
    cudaGetSymbolAddress((void**)&SPhi, g_SPhi); cudaGetSymbolAddress((void**)&SPlo, g_SPlo);
    cudaGetSymbolAddress((void**)&RPhi, g_RPhi); cudaGetSymbolAddress((void**)&RPlo, g_RPlo);
    cudaGetSymbolAddress((void**)&S32hi, g_S32hi); cudaGetSymbolAddress((void**)&S32lo, g_S32lo);
    cudaGetSymbolAddress((void**)&S64hi, g_S64hi); cudaGetSymbolAddress((void**)&S64lo, g_S64lo);
    cudaGetSymbolAddress((void**)&C1hi, g_C1hi); cudaGetSymbolAddress((void**)&C1lo, g_C1lo);
    cudaGetSymbolAddress((void**)&C2hi, g_C2hi); cudaGetSymbolAddress((void**)&C2lo, g_C2lo);
    cudaGetSymbolAddress((void**)&GChi, g_GChi); cudaGetSymbolAddress((void**)&GClo, g_GClo);
    cudaGetSymbolAddress((void**)&W8F, g_W8F);
    cudaGetSymbolAddress((void**)&sP1, g_sP1);
    cudaGetSymbolAddress((void**)&sP2, g_sP2);
    cudaGetSymbolAddress((void**)&sP3, g_sP3);
    cudaGetSymbolAddress((void**)&gbuf, g_gbuf);

    cudaFuncSetAttribute(tgemm_kernel,
        cudaFuncAttributeMaxDynamicSharedMemorySize, TG_SMEM);
    cudaFuncSetAttribute(phase2_kernel,
        cudaFuncAttributeMaxDynamicSharedMemorySize, P2_SMEM_FLOATS * 4);

    // ---- streams + events (created once; capture-safe fork/join) ----
    static cudaStream_t s2 = 0, s3 = 0;
    static cudaEvent_t evFork = 0, evX = 0, evS1 = 0, evPow = 0, evP2end = 0;
    static cudaEvent_t evP0[CH];
    static bool tried = false;
    if (!tried) {
        tried = true;
        if (cudaStreamCreateWithFlags(&s2, cudaStreamNonBlocking) != cudaSuccess)
            s2 = 0;
        if (cudaStreamCreateWithFlags(&s3, cudaStreamNonBlocking) != cudaSuccess)
            s3 = 0;
        cudaEventCreateWithFlags(&evFork, cudaEventDisableTiming);
        cudaEventCreateWithFlags(&evX,    cudaEventDisableTiming);
        cudaEventCreateWithFlags(&evS1,   cudaEventDisableTiming);
        cudaEventCreateWithFlags(&evPow,  cudaEventDisableTiming);
        cudaEventCreateWithFlags(&evP2end, cudaEventDisableTiming);
        for (int i = 0; i < CH; i++)
            cudaEventCreateWithFlags(&evP0[i], cudaEventDisableTiming);
    }

    cudaEventRecord(evFork, 0);
    cudaStreamWaitEvent(s2, evFork, 0);
    cudaStreamWaitEvent(s3, evFork, 0);

    // ======== s3: R-derived prep + full power chain ========
    bar_reset_kernel<<<(MAX_BAR + 255) / 256, 256, 0, s3>>>();
    transpose_split_kernel<<<dim3(32, 32), 256, 0, s3>>>(rker, SPhi, SPlo);    // S^1
    cudaEventRecord(evS1, s3);
    split_gather_kernel<<<UDIM, 256, 0, s3>>>(rker, NAT_B, NAT_C, RPhi, RPlo); // R^1
    copy_h0_kernel<<<(BATCH * UDIM + 255) / 256, 256, 0, s3>>>(h0, gbuf, GChi, GClo);
    {
        dim3 g1(8, 8), g2(8, 16), g4(8, 32), g8(8, 64);
        // S^2 = S^1 x R^1
        tgemm_kernel<<<g1, 256, TG_SMEM, s3>>>(SPhi, SPlo, NAT_B, NAT_C, RPhi, RPlo,
            nullptr, 0, 0, nullptr, 0, 0, SPhi + SL, SPlo + SL, NAT_B, NAT_C);
        // R^2 = R^1 x S^1
        tgemm_kernel<<<g1, 256, TG_SMEM, s3>>>(RPhi, RPlo, NAT_B, NAT_C, SPhi, SPlo,
            nullptr, 0, 0, nullptr, 0, 0, RPhi + SL, RPlo + SL, NAT_B, NAT_C);
        // S^3,4 = [S^1,S^2] x R^2
        tgemm_kernel<<<g2, 256, TG_SMEM, s3>>>(SPhi, SPlo, NAT_B, NAT_C,
            RPhi + SL, RPlo + SL,
            nullptr, 0, 0, nullptr, 0, 0, SPhi + 2 * SL, SPlo + 2 * SL, NAT_B, NAT_C);
        // R^4 = R^2 x S^2
        tgemm_kernel<<<g1, 256, TG_SMEM, s3>>>(RPhi + SL, RPlo + SL, NAT_B, NAT_C,
            SPhi + SL, SPlo + SL,
            nullptr, 0, 0, nullptr, 0, 0, RPhi + 2 * SL, RPlo + 2 * SL, NAT_B, NAT_C);
        // S^5..8 = [S^1..S^4] x R^4
        tgemm_kernel<<<g4, 256, TG_SMEM, s3>>>(SPhi, SPlo, NAT_B, NAT_C,
            RPhi + 2 * SL, RPlo + 2 * SL,
            nullptr, 0, 0, nullptr, 0, 0, SPhi + 4 * SL, SPlo + 4 * SL, NAT_B, NAT_C);
        // R^8 = R^4 x S^4
        tgemm_kernel<<<g1, 256, TG_SMEM, s3>>>(RPhi + 2 * SL, RPlo + 2 * SL, NAT_B, NAT_C,
            SPhi + 3 * SL, SPlo + 3 * SL,
            nullptr, 0, 0, nullptr, 0, 0, RPhi + 3 * SL, RPlo + 3 * SL, NAT_B, NAT_C);
        // S^9..16 = [S^1..S^8] x R^8
        tgemm_kernel<<<g8, 256, TG_SMEM, s3>>>(SPhi, SPlo, NAT_B, NAT_C,
            RPhi + 3 * SL, RPlo + 3 * SL,
            nullptr, 0, 0, nullptr, 0, 0, SPhi + 8 * SL, SPlo + 8 * SL, NAT_B, NAT_C);
        // R^16 = R^8 x S^8
        tgemm_kernel<<<g1, 256, TG_SMEM, s3>>>(RPhi + 3 * SL, RPlo + 3 * SL, NAT_B, NAT_C,
            SPhi + 7 * SL, SPlo + 7 * SL,
            nullptr, 0, 0, nullptr, 0, 0, RPhi + 4 * SL, RPlo + 4 * SL, NAT_B, NAT_C);
        // R^32 = R^16 x S^16
        tgemm_kernel<<<g1, 256, TG_SMEM, s3>>>(RPhi + 4 * SL, RPlo + 4 * SL, NAT_B, NAT_C,
            SPhi + 15 * SL, SPlo + 15 * SL,
            nullptr, 0, 0, nullptr, 0, 0, RPhi + 5 * SL, RPlo + 5 * SL, NAT_B, NAT_C);
        // S^32 = S^16 x R^16
        tgemm_kernel<<<g1, 256, TG_SMEM, s3>>>(SPhi + 15 * SL, SPlo + 15 * SL, NAT_B, NAT_C,
            RPhi + 4 * SL, RPlo + 4 * SL,
            nullptr, 0, 0, nullptr, 0, 0, S32hi, S32lo, NAT_B, NAT_C);
        // R^64 = R^32 x S^32
        tgemm_kernel<<<g1, 256, TG_SMEM, s3>>>(RPhi + 5 * SL, RPlo + 5 * SL, NAT_B, NAT_C,
            S32hi, S32lo,
            nullptr, 0, 0, nullptr, 0, 0, RPhi + 6 * SL, RPlo + 6 * SL, NAT_B, NAT_C);
        // S^64 = S^32 x R^32
        tgemm_kernel<<<g1, 256, TG_SMEM, s3>>>(S32hi, S32lo, NAT_B, NAT_C,
            RPhi + 5 * SL, RPlo + 5 * SL,
            nullptr, 0, 0, nullptr, 0, 0, S64hi, S64lo, NAT_B, NAT_C);
        // S^128 fp32 = S^64 x R^64
        tgemm_kernel<<<g1, 256, TG_SMEM, s3>>>(S64hi, S64lo, NAT_B, NAT_C,
            RPhi + 6 * SL, RPlo + 6 * SL,
            nullptr, 0, 0, W8F, NAT_B, NAT_C, nullptr, nullptr, 0, 0);
    }
    cudaEventRecord(evPow, s3);

    // ======== main: x prep ========
    transpose_split_kernel<<<dim3(32, 32), 256>>>(kern, KThi, KTlo);
    split_gather_kernel<<<BATCH * TDIM, 256>>>(x, NAT_B, NAT_C, Xhi, Xlo);
    cudaEventRecord(evX, 0);
    cudaStreamWaitEvent(s2, evX, 0);

    // ======== s2: phase 0 as 16 sub-GEMMs by t mod 16 (rows m = c*32+b) ====
    // A = X rows b*2048 + c*16 + j; Out fp32 -> out; P0_0 also emits the
    // chunk-head bf16 split (phase-1 seed) via OB.
    {
        dim3 gp(8, 32);   // M = 4096
        for (int j = 0; j < CH; j++) {
            tgemm_kernel<<<gp, 256, TG_SMEM, s2>>>(
                Xhi + (ll)j * 1024, Xlo + (ll)j * 1024, (ll)2048 * 1024, (ll)16 * 1024,
                KThi, KTlo,
                cst, 1024, 0,
                out + (ll)j * 1024, TU, CU,
                (j == 0) ? UAhi : nullptr, (j == 0) ? UAlo : nullptr, NAT_B, NAT_C);
            cudaEventRecord(evP0[j], s2);
        }
    }

    // ======== main: phase 1 Horner chain, pipelined against phase 0 ========
    cudaStreamWaitEvent(0, evS1, 0);
    cudaStreamWaitEvent(0, evP0[0], 0);
    {
        dim3 gp(8, 32);   // M = 4096
        for (int jj = 1; jj < CH; jj++) {
            const u16* ah = (jj & 1) ? UAhi : UBhi;
            const u16* al = (jj & 1) ? UAlo : UBlo;
            u16* oh = (jj & 1) ? UBhi : UAhi;
            u16* ol = (jj & 1) ? UBlo : UAlo;
            cudaStreamWaitEvent(0, evP0[jj], 0);
            tgemm_kernel<<<gp, 256, TG_SMEM>>>(ah, al, NAT_B, NAT_C,
                SPhi, SPlo,
                out + (ll)jj * 1024, TU, CU,
                out + (ll)jj * 1024, TU, CU,
                oh, ol, NAT_B, NAT_C);
        }
    }
    // s split (s_c = u_15) now lives in UBhi/UBlo (natural m = c*32+b)

    cudaStreamWaitEvent(0, evPow, 0);

    // ---- radix-8 carry reduction: W = R^16 ----
    const float* sBase = out + (ll)(CH - 1) * 1024;  // s_c fp32 at t = c*16+15

    // combine1: s'_d = s_{2d} W + s_{2d+1}   (M = 2048)
    tgemm_kernel<<<dim3(8, 16), 256, TG_SMEM>>>(UBhi, UBlo, NAT_B, 2 * NAT_C,
        SPhi + 15 * SL, SPlo + 15 * SL,
        sBase + CU, TU, 2 * CU,
        sP1, NAT_B, NAT_C,
        C1hi, C1lo, NAT_B, NAT_C);
    // combine2: s''_e = s'_{2e} W^2 + s'_{2e+1}   (M = 1024)
    tgemm_kernel<<<dim3(8, 8), 256, TG_SMEM>>>(C1hi, C1lo, NAT_B, 2 * NAT_C,
        S32hi, S32lo,
        sP1 + NAT_C, NAT_B, 2 * NAT_C,
        sP2, NAT_B, NAT_C,
        C2hi, C2lo, NAT_B, NAT_C);
    // combine3: s'''_f = s''_{2f} W^4 + s''_{2f+1}   (M = 512)
    tgemm_kernel<<<dim3(8, 4), 256, TG_SMEM>>>(C2hi, C2lo, NAT_B, 2 * NAT_C,
        S64hi, S64lo,
        sP2 + NAT_C, NAT_B, 2 * NAT_C,
        sP3, NAT_B, NAT_C,
        nullptr, nullptr, 0, 0);

    // serial chain (15 steps): g_{8(f+1)} = g_{8f} W^8 + s'''_f  (+ GC split)
    phase2_kernel<<<P2_CTAS, 256, P2_SMEM_FLOATS * 4>>>(
        W8F, sP3, NAT_B, NAT_C, gbuf, 8 * GB, GChi, GClo, 8 * NAT_C, 15);

    // backfill3: g_{8f+4} = g_{8f} W^4 + s''_{2f}   (M = 512)
    tgemm_kernel<<<dim3(8, 4), 256, TG_SMEM>>>(GChi, GClo, NAT_B, 8 * NAT_C,
        S64hi, S64lo,
        sP2, NAT_B, 2 * NAT_C,
        nullptr, 0, 0,
        GChi + 4 * NAT_C, GClo + 4 * NAT_C, NAT_B, 8 * NAT_C);
    // backfill2: g_{4e+2} = g_{4e} W^2 + s'_{2e}   (M = 1024)
    tgemm_kernel<<<dim3(8, 8), 256, TG_SMEM>>>(GChi, GClo, NAT_B, 4 * NAT_C,
        S32hi, S32lo,
        sP1, NAT_B, 2 * NAT_C,
        nullptr, 0, 0,
        GChi + 2 * NAT_C, GClo + 2 * NAT_C, NAT_B, 4 * NAT_C);
    // backfill1: g_{2d+1} = g_{2d} W + s_{2d}   (M = 2048)
    tgemm_kernel<<<dim3(8, 16), 256, TG_SMEM>>>(GChi, GClo, NAT_B, 2 * NAT_C,
        SPhi + 15 * SL, SPlo + 15 * SL,
        sBase, TU, 2 * CU,
        nullptr, 0, 0,
        GChi + NAT_C, GClo + NAT_C, NAT_B, 2 * NAT_C);

    // phase 3 (single GEMM): out_{c*16+j} += g_c @ R^{j+1} for all j at once.
    tgemm_kernel<<<dim3(128, 32), 256, TG_SMEM>>>(GChi, GClo, NAT_B, NAT_C,
        SPhi, SPlo,
        out, TU, CU,
        out, TU, CU,
        nullptr, nullptr, 0, 0);
}